// round 2
// baseline (speedup 1.0000x reference)
#include <cuda_runtime.h>
#include <cuda_bf16.h>
#include <math.h>

// Problem constants
#define Bb 4
#define Ss 2048
#define Tt 2048
#define Hh 1024
#define Aa 1024
#define NHEAD 16
#define HDIM 64

// Scratch (device globals: allocation-guard-safe)
__device__ float d_q[(size_t)Bb * Ss * Aa];
__device__ float d_k[(size_t)Bb * Tt * Aa];
__device__ float d_v[(size_t)Bb * Tt * Aa];
__device__ float d_o[(size_t)Bb * Ss * Aa];
__device__ float d_maskf[Bb * Tt];
__device__ int d_maskmode;

// ---------------------------------------------------------------------------
// Mask dtype detection: mask may arrive as bool8 (1B), int32, or float32.
// Inspect first 2048 32-bit words (8192 bytes = safe under all 3 layouts).
//   - words all in {0, 0x3F800000} with at least one 1.0f  -> float32
//   - words all in {0, 1}                                  -> int32
//   - otherwise                                            -> bool bytes
// ---------------------------------------------------------------------------
__global__ void detect_mask_kernel(const unsigned char* __restrict__ m) {
    const unsigned int* w = (const unsigned int*)m;
    int okf = 1, oki = 1, anyf = 0;
    for (int i = threadIdx.x; i < 2048; i += blockDim.x) {
        unsigned int v = w[i];
        if (v != 0u && v != 0x3F800000u) okf = 0;
        if (v == 0x3F800000u) anyf = 1;
        if (v > 1u) oki = 0;
    }
    okf = __syncthreads_and(okf);
    anyf = __syncthreads_or(anyf);
    oki = __syncthreads_and(oki);
    if (threadIdx.x == 0) d_maskmode = (okf && anyf) ? 0 : (oki ? 1 : 2);
}

__global__ void convert_mask_kernel(const unsigned char* __restrict__ m) {
    int i = blockIdx.x * blockDim.x + threadIdx.x;
    if (i >= Bb * Tt) return;
    int mode = d_maskmode;
    float v;
    if (mode == 0)      v = ((const float*)m)[i];
    else if (mode == 1) v = (float)((const int*)m)[i];
    else                v = (float)m[i];
    d_maskf[i] = (v != 0.0f) ? 1.0f : 0.0f;
}

// ---------------------------------------------------------------------------
// SGEMM: C[M,N] = A[M,K] @ W[K,N] + bias[N]   (all fp32, row-major)
// 128x128 block, BK=16, 256 threads, 8x8 per thread.
// ---------------------------------------------------------------------------
__global__ __launch_bounds__(256, 1)
void sgemm_bias(const float* __restrict__ A, const float* __restrict__ W,
                const float* __restrict__ bias, float* __restrict__ C,
                int M, int N, int K) {
    __shared__ float As[16][128];   // k-major
    __shared__ float Ws[16][128];
    const int tid = threadIdx.x;
    const int tx = tid & 15, ty = tid >> 4;
    const int row0 = blockIdx.y * 128;
    const int col0 = blockIdx.x * 128;

    float acc[8][8];
#pragma unroll
    for (int i = 0; i < 8; i++)
#pragma unroll
        for (int j = 0; j < 8; j++) acc[i][j] = 0.f;

    for (int k0 = 0; k0 < K; k0 += 16) {
#pragma unroll
        for (int l = 0; l < 2; l++) {
            int i = tid + l * 256;        // float4 index, 0..511
            int r = i >> 2;               // 0..127
            int c = (i & 3) << 2;         // 0,4,8,12
            float4 v = *(const float4*)&A[(size_t)(row0 + r) * K + k0 + c];
            As[c + 0][r] = v.x; As[c + 1][r] = v.y;
            As[c + 2][r] = v.z; As[c + 3][r] = v.w;
        }
#pragma unroll
        for (int l = 0; l < 2; l++) {
            int i = tid + l * 256;
            int r = i >> 5;               // 0..15
            int c = (i & 31) << 2;        // 0..124
            *(float4*)&Ws[r][c] = *(const float4*)&W[(size_t)(k0 + r) * N + col0 + c];
        }
        __syncthreads();
#pragma unroll
        for (int kk = 0; kk < 16; kk++) {
            float4 a0 = *(const float4*)&As[kk][ty * 8];
            float4 a1 = *(const float4*)&As[kk][ty * 8 + 4];
            float4 b0 = *(const float4*)&Ws[kk][tx * 8];
            float4 b1 = *(const float4*)&Ws[kk][tx * 8 + 4];
            float ra[8] = {a0.x, a0.y, a0.z, a0.w, a1.x, a1.y, a1.z, a1.w};
            float rb[8] = {b0.x, b0.y, b0.z, b0.w, b1.x, b1.y, b1.z, b1.w};
#pragma unroll
            for (int i = 0; i < 8; i++)
#pragma unroll
                for (int j = 0; j < 8; j++)
                    acc[i][j] = fmaf(ra[i], rb[j], acc[i][j]);
        }
        __syncthreads();
    }

#pragma unroll
    for (int i = 0; i < 8; i++) {
        size_t r = row0 + ty * 8 + i;
#pragma unroll
        for (int j = 0; j < 8; j += 4) {
            int c = col0 + tx * 8 + j;
            float4 b4 = *(const float4*)&bias[c];
            float4 o;
            o.x = acc[i][j + 0] + b4.x;
            o.y = acc[i][j + 1] + b4.y;
            o.z = acc[i][j + 2] + b4.z;
            o.w = acc[i][j + 3] + b4.w;
            *(float4*)&C[r * N + c] = o;
        }
    }
}

// ---------------------------------------------------------------------------
// Flash attention: grid (S/64, NH, B), 256 threads, 64x64 q-tile x 64 k-tile.
// Thread (ty,tx) owns a 4x4 micro-tile. Online softmax, exact reference
// masking semantics (masked logits == -100000 exactly).
// ---------------------------------------------------------------------------
#define QLD 68   // 64 + 4 pad, keeps float4 alignment, kills bank conflicts

__global__ __launch_bounds__(256, 1)
void attn_kernel() {
    extern __shared__ float smf[];
    float* Qts  = smf;                 // [64 d][QLD] (d-major, pre-scaled)
    float* KPs  = Qts + 64 * QLD;      // K tile d-major [64][QLD], reused as P [64 r][QLD]
    float* Vs   = KPs + 64 * QLD;      // [64 t][64 d]
    float* redm = Vs + 64 * 64;        // [64][16] row-max partials
    float* reds = redm + 64 * 16;      // [64][16] row-sum partials

    const int sq = blockIdx.x;
    const int h  = blockIdx.y;
    const int b  = blockIdx.z;
    const int tid = threadIdx.x;
    const int tx = tid & 15, ty = tid >> 4;
    const int r0 = ty * 4, c0 = tx * 4;

    // Load Q tile (transposed to d-major), scaled by 1/sqrt(HD)
    const float* qbase = d_q + ((size_t)b * Ss + sq * 64) * Aa + h * HDIM;
#pragma unroll
    for (int l = 0; l < 16; l++) {
        int idx = tid + l * 256;
        int i = idx >> 6, d = idx & 63;
        Qts[d * QLD + i] = qbase[(size_t)i * Aa + d] * 0.125f;
    }

    float m_old[4], l_acc[4], oa[4][4];
#pragma unroll
    for (int i = 0; i < 4; i++) {
        m_old[i] = -INFINITY; l_acc[i] = 0.f;
#pragma unroll
        for (int j = 0; j < 4; j++) oa[i][j] = 0.f;
    }

    for (int kt = 0; kt < Tt / 64; kt++) {
        __syncthreads();  // prior PV reads of KPs/Vs complete
        const float* kbase = d_k + ((size_t)b * Tt + kt * 64) * Aa + h * HDIM;
        const float* vbase = d_v + ((size_t)b * Tt + kt * 64) * Aa + h * HDIM;
#pragma unroll
        for (int l = 0; l < 16; l++) {
            int idx = tid + l * 256;
            int j = idx >> 6, d = idx & 63;
            KPs[d * QLD + j] = kbase[(size_t)j * Aa + d];
            Vs[j * 64 + d]   = vbase[(size_t)j * Aa + d];
        }
        float mk[4];
#pragma unroll
        for (int j = 0; j < 4; j++) mk[j] = d_maskf[b * Tt + kt * 64 + c0 + j];
        __syncthreads();

        // S = Q K^T  (Q pre-scaled)
        float s[4][4];
#pragma unroll
        for (int i = 0; i < 4; i++)
#pragma unroll
            for (int j = 0; j < 4; j++) s[i][j] = 0.f;
#pragma unroll 8
        for (int d = 0; d < 64; d++) {
            float4 qa = *(const float4*)&Qts[d * QLD + r0];
            float4 kb = *(const float4*)&KPs[d * QLD + c0];
            float qv[4] = {qa.x, qa.y, qa.z, qa.w};
            float kv[4] = {kb.x, kb.y, kb.z, kb.w};
#pragma unroll
            for (int i = 0; i < 4; i++)
#pragma unroll
                for (int j = 0; j < 4; j++)
                    s[i][j] = fmaf(qv[i], kv[j], s[i][j]);
        }
        // masking: exact reference semantics (masked -> -100000)
#pragma unroll
        for (int i = 0; i < 4; i++)
#pragma unroll
            for (int j = 0; j < 4; j++)
                s[i][j] = (mk[j] != 0.f) ? s[i][j] : -100000.0f;

        // tile row-max -> m_new
#pragma unroll
        for (int i = 0; i < 4; i++) {
            float pm = fmaxf(fmaxf(s[i][0], s[i][1]), fmaxf(s[i][2], s[i][3]));
            redm[(r0 + i) * 16 + tx] = pm;
        }
        __syncthreads();   // also guarantees all s-compute done reading KPs
        float m_new[4], alpha[4];
#pragma unroll
        for (int i = 0; i < 4; i++) {
            float tm = -INFINITY;
#pragma unroll
            for (int t = 0; t < 16; t++) tm = fmaxf(tm, redm[(r0 + i) * 16 + t]);
            m_new[i] = fmaxf(m_old[i], tm);
            alpha[i] = __expf(m_old[i] - m_new[i]);
        }
        // p = exp(s - m_new), row-sum partials, write P over the K buffer
#pragma unroll
        for (int i = 0; i < 4; i++) {
            float psum = 0.f;
#pragma unroll
            for (int j = 0; j < 4; j++) {
                float p = __expf(s[i][j] - m_new[i]);
                s[i][j] = p;
                psum += p;
            }
            reds[(r0 + i) * 16 + tx] = psum;
            float4 p4 = {s[i][0], s[i][1], s[i][2], s[i][3]};
            *(float4*)&KPs[(r0 + i) * QLD + c0] = p4;
        }
        __syncthreads();
#pragma unroll
        for (int i = 0; i < 4; i++) {
            float ls = 0.f;
#pragma unroll
            for (int t = 0; t < 16; t++) ls += reds[(r0 + i) * 16 + t];
            l_acc[i] = l_acc[i] * alpha[i] + ls;
#pragma unroll
            for (int j = 0; j < 4; j++) oa[i][j] *= alpha[i];
        }
        // O += P @ V
#pragma unroll 4
        for (int t = 0; t < 64; t++) {
            float4 vv = *(const float4*)&Vs[t * 64 + c0];
            float vr[4] = {vv.x, vv.y, vv.z, vv.w};
            float pr[4];
#pragma unroll
            for (int i = 0; i < 4; i++) pr[i] = KPs[(r0 + i) * QLD + t];
#pragma unroll
            for (int i = 0; i < 4; i++)
#pragma unroll
                for (int j = 0; j < 4; j++)
                    oa[i][j] = fmaf(pr[i], vr[j], oa[i][j]);
        }
#pragma unroll
        for (int i = 0; i < 4; i++) m_old[i] = m_new[i];
    }

    // epilogue: O / l
    float* obase = d_o + ((size_t)b * Ss + sq * 64) * Aa + h * HDIM;
#pragma unroll
    for (int i = 0; i < 4; i++) {
        float inv = 1.0f / l_acc[i];
        float4 o4 = {oa[i][0] * inv, oa[i][1] * inv, oa[i][2] * inv, oa[i][3] * inv};
        *(float4*)&obase[(size_t)(r0 + i) * Aa + c0] = o4;
    }
}

// ---------------------------------------------------------------------------
// Launch. Inputs (metadata order): x, y, mask, wq, bq, wk, bk, wv, bv, wo, bo
// ---------------------------------------------------------------------------
#define ATTN_SMEM_BYTES ((64 * QLD * 2 + 64 * 64 + 64 * 16 * 2) * (int)sizeof(float))

extern "C" void kernel_launch(void* const* d_in, const int* in_sizes, int n_in,
                              void* d_out, int out_size) {
    const float* x  = (const float*)d_in[0];
    const float* y  = (const float*)d_in[1];
    const unsigned char* mask = (const unsigned char*)d_in[2];
    const float* wq = (const float*)d_in[3];
    const float* bq = (const float*)d_in[4];
    const float* wk = (const float*)d_in[5];
    const float* bk = (const float*)d_in[6];
    const float* wv = (const float*)d_in[7];
    const float* bv = (const float*)d_in[8];
    const float* wo = (const float*)d_in[9];
    const float* bo = (const float*)d_in[10];
    float* out = (float*)d_out;

    float *pq, *pk, *pv, *po;
    cudaGetSymbolAddress((void**)&pq, d_q);
    cudaGetSymbolAddress((void**)&pk, d_k);
    cudaGetSymbolAddress((void**)&pv, d_v);
    cudaGetSymbolAddress((void**)&po, d_o);

    detect_mask_kernel<<<1, 256>>>(mask);
    convert_mask_kernel<<<(Bb * Tt + 255) / 256, 256>>>(mask);

    dim3 gP(Aa / 128, (Bb * Ss) / 128);
    sgemm_bias<<<gP, 256>>>(x, wq, bq, pq, Bb * Ss, Aa, Hh);
    sgemm_bias<<<gP, 256>>>(y, wk, bk, pk, Bb * Tt, Aa, Hh);
    sgemm_bias<<<gP, 256>>>(y, wv, bv, pv, Bb * Tt, Aa, Hh);

    cudaFuncSetAttribute(attn_kernel, cudaFuncAttributeMaxDynamicSharedMemorySize,
                         ATTN_SMEM_BYTES);
    attn_kernel<<<dim3(Ss / 64, NHEAD, Bb), 256, ATTN_SMEM_BYTES>>>();

    dim3 gO(Hh / 128, (Bb * Ss) / 128);
    sgemm_bias<<<gO, 256>>>(po, wo, bo, out, Bb * Ss, Hh, Aa);
}

// round 5
// speedup vs baseline: 3.0594x; 3.0594x over previous
#include <cuda_runtime.h>
#include <cuda_bf16.h>
#include <math.h>

// Problem constants
#define Bb 4
#define Ss 2048
#define Tt 2048
#define Hh 1024
#define Aa 1024
#define NHEAD 16
#define HDIM 64

typedef __nv_bfloat16 bf16;

// ---------------------------------------------------------------------------
// Scratch (device globals: allocation-guard-safe). All bf16 split pairs.
// ---------------------------------------------------------------------------
#define NACT (8192 * 1024)
#define NWGT (1024 * 1024)
__device__ bf16 g_xh[NACT], g_xl[NACT];
__device__ bf16 g_yh[NACT], g_yl[NACT];
__device__ bf16 g_wqh[NWGT], g_wql[NWGT];
__device__ bf16 g_wkh[NWGT], g_wkl[NWGT];
__device__ bf16 g_wvh[NWGT], g_wvl[NWGT];
__device__ bf16 g_woh[NWGT], g_wol[NWGT];
__device__ bf16 g_qh[NACT], g_ql[NACT];
__device__ bf16 g_kh[NACT], g_kl[NACT];
__device__ bf16 g_vh[NACT], g_vl[NACT];
__device__ bf16 g_oh[NACT], g_ol[NACT];
__device__ float d_maskf[Bb * Tt];
__device__ int d_maskmode;

// ---------------------------------------------------------------------------
// PTX helpers
// ---------------------------------------------------------------------------
__device__ __forceinline__ unsigned pack2(float lo, float hi) {
    unsigned r;
    asm("cvt.rn.bf16x2.f32 %0, %1, %2;" : "=r"(r) : "f"(hi), "f"(lo));
    return r;
}
__device__ __forceinline__ float lo16f(unsigned u) { return __uint_as_float(u << 16); }
__device__ __forceinline__ float hi16f(unsigned u) { return __uint_as_float(u & 0xFFFF0000u); }

__device__ __forceinline__ void mma16816(float* c, const unsigned* a, const unsigned* b) {
    asm volatile(
        "mma.sync.aligned.m16n8k16.row.col.f32.bf16.bf16.f32 "
        "{%0,%1,%2,%3}, {%4,%5,%6,%7}, {%8,%9}, {%0,%1,%2,%3};\n"
        : "+f"(c[0]), "+f"(c[1]), "+f"(c[2]), "+f"(c[3])
        : "r"(a[0]), "r"(a[1]), "r"(a[2]), "r"(a[3]), "r"(b[0]), "r"(b[1]));
}
__device__ __forceinline__ unsigned s2u(const void* p) {
    return (unsigned)__cvta_generic_to_shared(p);
}
__device__ __forceinline__ void ldsm4(unsigned* r, unsigned addr) {
    asm volatile("ldmatrix.sync.aligned.m8n8.x4.shared.b16 {%0,%1,%2,%3}, [%4];\n"
                 : "=r"(r[0]), "=r"(r[1]), "=r"(r[2]), "=r"(r[3]) : "r"(addr));
}
__device__ __forceinline__ void ldsm4t(unsigned* r, unsigned addr) {
    asm volatile("ldmatrix.sync.aligned.m8n8.x4.trans.shared.b16 {%0,%1,%2,%3}, [%4];\n"
                 : "=r"(r[0]), "=r"(r[1]), "=r"(r[2]), "=r"(r[3]) : "r"(addr));
}
__device__ __forceinline__ void cpasync16(unsigned sdst, const void* gsrc) {
    asm volatile("cp.async.cg.shared.global [%0], [%1], 16;\n" :: "r"(sdst), "l"(gsrc));
}
#define CP_COMMIT asm volatile("cp.async.commit_group;\n")
#define CP_WAIT0 asm volatile("cp.async.wait_group 0;\n")
#define CP_WAIT1 asm volatile("cp.async.wait_group 1;\n")

// ---------------------------------------------------------------------------
// Mask dtype detection (bool8 / int32 / float32) + conversion
// ---------------------------------------------------------------------------
__global__ void detect_mask_kernel(const unsigned char* __restrict__ m) {
    const unsigned int* w = (const unsigned int*)m;
    int okf = 1, oki = 1, anyf = 0;
    for (int i = threadIdx.x; i < 2048; i += blockDim.x) {
        unsigned int v = w[i];
        if (v != 0u && v != 0x3F800000u) okf = 0;
        if (v == 0x3F800000u) anyf = 1;
        if (v > 1u) oki = 0;
    }
    okf = __syncthreads_and(okf);
    anyf = __syncthreads_or(anyf);
    oki = __syncthreads_and(oki);
    if (threadIdx.x == 0) d_maskmode = (okf && anyf) ? 0 : (oki ? 1 : 2);
}

__global__ void convert_mask_kernel(const unsigned char* __restrict__ m) {
    int i = blockIdx.x * blockDim.x + threadIdx.x;
    if (i >= Bb * Tt) return;
    int mode = d_maskmode;
    float v;
    if (mode == 0)      v = ((const float*)m)[i];
    else if (mode == 1) v = (float)((const int*)m)[i];
    else                v = (float)m[i];
    d_maskf[i] = (v != 0.0f) ? 1.0f : 0.0f;
}

// ---------------------------------------------------------------------------
// fp32 -> (hi, lo) bf16 split, vectorized by 4
// ---------------------------------------------------------------------------
__global__ void split2_kernel(const float4* __restrict__ src, uint2* __restrict__ hi,
                              uint2* __restrict__ lo, int n4) {
    int i = blockIdx.x * blockDim.x + threadIdx.x;
    if (i >= n4) return;
    float4 v = src[i];
    unsigned h01 = pack2(v.x, v.y);
    unsigned h23 = pack2(v.z, v.w);
    float r0 = v.x - lo16f(h01);
    float r1 = v.y - hi16f(h01);
    float r2 = v.z - lo16f(h23);
    float r3 = v.w - hi16f(h23);
    hi[i] = make_uint2(h01, h23);
    lo[i] = make_uint2(pack2(r0, r1), pack2(r2, r3));
}

// ---------------------------------------------------------------------------
// Split-precision bf16 tensor-core GEMM:
// C = (Ah+Al)(Wh+Wl) + bias  ~= Ah*Wh + Al*Wh + Ah*Wl   (3 phases)
// Block 128x128, BK=32, 8 warps (2x4), warp tile 64x32, mma m16n8k16.
// Output: either split bf16 (Ch/Cl) or fp32 (Cf).
// ---------------------------------------------------------------------------
__global__ __launch_bounds__(256, 2)
void gemm_split(const bf16* __restrict__ Ah, const bf16* __restrict__ Al,
                const bf16* __restrict__ Wh, const bf16* __restrict__ Wl,
                const float* __restrict__ bias,
                bf16* __restrict__ Ch, bf16* __restrict__ Cl,
                float* __restrict__ Cf, int M, int N, int K) {
    __shared__ bf16 As[2][128 * 40];    // rows padded 32->40 elems (80B, conflict-free)
    __shared__ bf16 Ws[2][32 * 136];    // rows padded 128->136 elems (272B)

    const int tid = threadIdx.x;
    const int wid = tid >> 5, lane = tid & 31;
    const int wm = wid >> 2, wn = wid & 3;
    const int g = lane >> 2, tig = lane & 3;
    const int row0 = blockIdx.y * 128, col0 = blockIdx.x * 128;

    float acc[4][4][4];
#pragma unroll
    for (int i = 0; i < 4; i++)
#pragma unroll
        for (int j = 0; j < 4; j++)
#pragma unroll
            for (int k = 0; k < 4; k++) acc[i][j][k] = 0.f;

#pragma unroll 1
    for (int ph = 0; ph < 3; ph++) {
        const bf16* Ap = (ph == 1) ? Al : Ah;
        const bf16* Wp = (ph == 2) ? Wl : Wh;

        // preload k0 = 0 into stage 0
#pragma unroll
        for (int l = 0; l < 2; l++) {
            int c = tid + l * 256;
            int ar = c >> 2, ac = (c & 3) * 8;
            cpasync16(s2u(&As[0][ar * 40 + ac]), Ap + (size_t)(row0 + ar) * K + ac);
            int wr = c >> 4, wc = (c & 15) * 8;
            cpasync16(s2u(&Ws[0][wr * 136 + wc]), Wp + (size_t)wr * N + col0 + wc);
        }
        CP_COMMIT;

        int stage = 0;
        for (int k0 = 0; k0 < K; k0 += 32) {
            if (k0 + 32 < K) {
                int st = stage ^ 1, kn = k0 + 32;
#pragma unroll
                for (int l = 0; l < 2; l++) {
                    int c = tid + l * 256;
                    int ar = c >> 2, ac = (c & 3) * 8;
                    cpasync16(s2u(&As[st][ar * 40 + ac]),
                              Ap + (size_t)(row0 + ar) * K + kn + ac);
                    int wr = c >> 4, wc = (c & 15) * 8;
                    cpasync16(s2u(&Ws[st][wr * 136 + wc]),
                              Wp + (size_t)(kn + wr) * N + col0 + wc);
                }
                CP_COMMIT;
                CP_WAIT1;
            } else {
                CP_WAIT0;
            }
            __syncthreads();

#pragma unroll
            for (int kk = 0; kk < 32; kk += 16) {
                unsigned af[4][4];
#pragma unroll
                for (int mf = 0; mf < 4; mf++)
                    ldsm4(af[mf], s2u(&As[stage][(wm * 64 + mf * 16 + (lane & 15)) * 40 +
                                                 kk + 8 * (lane >> 4)]));
                unsigned bfr[2][4];
#pragma unroll
                for (int n2 = 0; n2 < 2; n2++)
                    ldsm4t(bfr[n2], s2u(&Ws[stage][(kk + (lane & 15)) * 136 + wn * 32 +
                                                   n2 * 16 + 8 * (lane >> 4)]));
#pragma unroll
                for (int mf = 0; mf < 4; mf++)
#pragma unroll
                    for (int nf = 0; nf < 4; nf++)
                        mma16816(acc[mf][nf], af[mf], &bfr[nf >> 1][(nf & 1) * 2]);
            }
            __syncthreads();
            stage ^= 1;
        }
    }

    // epilogue
#pragma unroll
    for (int mf = 0; mf < 4; mf++) {
        size_t r1 = (size_t)(row0 + wm * 64 + mf * 16 + g);
#pragma unroll
        for (int nf = 0; nf < 4; nf++) {
            int c = col0 + wn * 32 + nf * 8 + tig * 2;
            float2 b2 = *(const float2*)&bias[c];
            float v00 = acc[mf][nf][0] + b2.x, v01 = acc[mf][nf][1] + b2.y;
            float v10 = acc[mf][nf][2] + b2.x, v11 = acc[mf][nf][3] + b2.y;
            if (Cf) {
                *(float2*)&Cf[r1 * N + c] = make_float2(v00, v01);
                *(float2*)&Cf[(r1 + 8) * N + c] = make_float2(v10, v11);
            } else {
                unsigned h0 = pack2(v00, v01);
                *(unsigned*)(Ch + r1 * N + c) = h0;
                *(unsigned*)(Cl + r1 * N + c) = pack2(v00 - lo16f(h0), v01 - hi16f(h0));
                unsigned h1 = pack2(v10, v11);
                *(unsigned*)(Ch + (r1 + 8) * N + c) = h1;
                *(unsigned*)(Cl + (r1 + 8) * N + c) = pack2(v10 - lo16f(h1), v11 - hi16f(h1));
            }
        }
    }
}

// ---------------------------------------------------------------------------
// Flash attention with mma.sync, split-bf16 precision.
// Block: 128 q-rows, 8 warps (16 rows each, full t=64 per warp -> warp-local
// softmax via shfl). Double-buffered cp.async K/V tiles.
// ---------------------------------------------------------------------------
#define AT_PAD 72              // 64 + 8 elems (144B rows, conflict-free ldmatrix)
#define AT_TILE (64 * AT_PAD)  // 4608 elems
#define AT_BUF (4 * AT_TILE)   // KH, KL, VH, VL
#define ATT_SMEM_BYTES (2 * AT_BUF * 2)

__global__ __launch_bounds__(256)
void attn_mma() {
    extern __shared__ bf16 sm[];
    const int sq = blockIdx.x, h = blockIdx.y, b = blockIdx.z;
    const int tid = threadIdx.x, wid = tid >> 5, lane = tid & 31;
    const int g = lane >> 2, tig = lane & 3;

    // Q fragments (hi, lo), 4 d-chunks of 16
    unsigned qh[4][4], ql[4][4];
    {
        size_t rbase = ((size_t)b * Ss + sq * 128 + wid * 16) * Aa + h * HDIM;
        size_t o00 = rbase + (size_t)g * Aa + tig * 2;
#pragma unroll
        for (int dc = 0; dc < 4; dc++) {
            size_t o = o00 + dc * 16;
            qh[dc][0] = *(const unsigned*)(g_qh + o);
            qh[dc][1] = *(const unsigned*)(g_qh + o + (size_t)8 * Aa);
            qh[dc][2] = *(const unsigned*)(g_qh + o + 8);
            qh[dc][3] = *(const unsigned*)(g_qh + o + (size_t)8 * Aa + 8);
            ql[dc][0] = *(const unsigned*)(g_ql + o);
            ql[dc][1] = *(const unsigned*)(g_ql + o + (size_t)8 * Aa);
            ql[dc][2] = *(const unsigned*)(g_ql + o + 8);
            ql[dc][3] = *(const unsigned*)(g_ql + o + (size_t)8 * Aa + 8);
        }
    }

    float oacc[8][4];
#pragma unroll
    for (int i = 0; i < 8; i++)
#pragma unroll
        for (int j = 0; j < 4; j++) oacc[i][j] = 0.f;
    float mo0 = -INFINITY, mo1 = -INFINITY, l0 = 0.f, l1 = 0.f;

    auto load_tiles = [&](int it, int bb) {
        const size_t base = ((size_t)b * Tt + it * 64) * Aa + h * HDIM;
#pragma unroll
        for (int l = 0; l < 8; l++) {
            int c = tid + l * 256;
            int mat = c >> 9, r = (c >> 3) & 63, ch = c & 7;
            const bf16* src = (mat == 0 ? g_kh : mat == 1 ? g_kl : mat == 2 ? g_vh : g_vl)
                              + base + (size_t)r * Aa + ch * 8;
            cpasync16(s2u(sm + bb * AT_BUF + mat * AT_TILE + r * AT_PAD + ch * 8), src);
        }
    };

    load_tiles(0, 0);
    CP_COMMIT;
    const int NIT = Tt / 64;

#pragma unroll 1
    for (int it = 0; it < NIT; it++) {
        int bb = it & 1;
        if (it + 1 < NIT) { load_tiles(it + 1, bb ^ 1); CP_COMMIT; CP_WAIT1; }
        else               { CP_WAIT0; }
        __syncthreads();

        const bf16* KH = sm + bb * AT_BUF;
        const bf16* KL = KH + AT_TILE;
        const bf16* VH = KH + 2 * AT_TILE;
        const bf16* VL = KH + 3 * AT_TILE;

        // ---- S = (Qh+Ql) (Kh+Kl)^T  (drop lo*lo) ----
        float s[8][4];
#pragma unroll
        for (int i = 0; i < 8; i++)
#pragma unroll
            for (int j = 0; j < 4; j++) s[i][j] = 0.f;

        const int ktrow = ((lane >> 4) & 1) * 8 + (lane & 7);
        const int kdoff = ((lane >> 3) & 1) * 8;
#pragma unroll
        for (int dc = 0; dc < 4; dc++) {
#pragma unroll
            for (int j = 0; j < 4; j++) {
                unsigned kf[4];
                ldsm4(kf, s2u(KH + (j * 16 + ktrow) * AT_PAD + dc * 16 + kdoff));
                mma16816(s[2 * j], qh[dc], kf);
                mma16816(s[2 * j + 1], qh[dc], kf + 2);
                mma16816(s[2 * j], ql[dc], kf);
                mma16816(s[2 * j + 1], ql[dc], kf + 2);
            }
        }
#pragma unroll
        for (int dc = 0; dc < 4; dc++) {
#pragma unroll
            for (int j = 0; j < 4; j++) {
                unsigned kf[4];
                ldsm4(kf, s2u(KL + (j * 16 + ktrow) * AT_PAD + dc * 16 + kdoff));
                mma16816(s[2 * j], qh[dc], kf);
                mma16816(s[2 * j + 1], qh[dc], kf + 2);
            }
        }

        // ---- scale + mask + online softmax (warp-local rows) ----
        const float* mrow = d_maskf + b * Tt + it * 64;
        float mt0 = -INFINITY, mt1 = -INFINITY;
#pragma unroll
        for (int n = 0; n < 8; n++) {
            float2 m2 = *(const float2*)&mrow[n * 8 + tig * 2];
            s[n][0] = (m2.x != 0.f) ? s[n][0] * 0.125f : -100000.0f;
            s[n][1] = (m2.y != 0.f) ? s[n][1] * 0.125f : -100000.0f;
            s[n][2] = (m2.x != 0.f) ? s[n][2] * 0.125f : -100000.0f;
            s[n][3] = (m2.y != 0.f) ? s[n][3] * 0.125f : -100000.0f;
            mt0 = fmaxf(mt0, fmaxf(s[n][0], s[n][1]));
            mt1 = fmaxf(mt1, fmaxf(s[n][2], s[n][3]));
        }
        mt0 = fmaxf(mt0, __shfl_xor_sync(0xFFFFFFFFu, mt0, 1));
        mt0 = fmaxf(mt0, __shfl_xor_sync(0xFFFFFFFFu, mt0, 2));
        mt1 = fmaxf(mt1, __shfl_xor_sync(0xFFFFFFFFu, mt1, 1));
        mt1 = fmaxf(mt1, __shfl_xor_sync(0xFFFFFFFFu, mt1, 2));
        float mn0 = fmaxf(mo0, mt0), mn1 = fmaxf(mo1, mt1);
        float a0 = __expf(mo0 - mn0), a1 = __expf(mo1 - mn1);
        float ls0 = 0.f, ls1 = 0.f;
#pragma unroll
        for (int n = 0; n < 8; n++) {
            s[n][0] = __expf(s[n][0] - mn0);
            s[n][1] = __expf(s[n][1] - mn0);
            s[n][2] = __expf(s[n][2] - mn1);
            s[n][3] = __expf(s[n][3] - mn1);
            ls0 += s[n][0] + s[n][1];
            ls1 += s[n][2] + s[n][3];
        }
        ls0 += __shfl_xor_sync(0xFFFFFFFFu, ls0, 1);
        ls0 += __shfl_xor_sync(0xFFFFFFFFu, ls0, 2);
        ls1 += __shfl_xor_sync(0xFFFFFFFFu, ls1, 1);
        ls1 += __shfl_xor_sync(0xFFFFFFFFu, ls1, 2);
        l0 = l0 * a0 + ls0;
        l1 = l1 * a1 + ls1;
#pragma unroll
        for (int nd = 0; nd < 8; nd++) {
            oacc[nd][0] *= a0; oacc[nd][1] *= a0;
            oacc[nd][2] *= a1; oacc[nd][3] *= a1;
        }
        mo0 = mn0; mo1 = mn1;

        // ---- O += (Ph+Pl)(Vh+Vl)  (drop lo*lo) ----
        const int vtrow = lane & 15;
        const int vdoff = (lane >> 4) * 8;
#pragma unroll
        for (int tc = 0; tc < 4; tc++) {
            unsigned pfh[4], pfl[4];
            pfh[0] = pack2(s[2 * tc][0], s[2 * tc][1]);
            pfh[1] = pack2(s[2 * tc][2], s[2 * tc][3]);
            pfh[2] = pack2(s[2 * tc + 1][0], s[2 * tc + 1][1]);
            pfh[3] = pack2(s[2 * tc + 1][2], s[2 * tc + 1][3]);
            pfl[0] = pack2(s[2 * tc][0] - lo16f(pfh[0]), s[2 * tc][1] - hi16f(pfh[0]));
            pfl[1] = pack2(s[2 * tc][2] - lo16f(pfh[1]), s[2 * tc][3] - hi16f(pfh[1]));
            pfl[2] = pack2(s[2 * tc + 1][0] - lo16f(pfh[2]), s[2 * tc + 1][1] - hi16f(pfh[2]));
            pfl[3] = pack2(s[2 * tc + 1][2] - lo16f(pfh[3]), s[2 * tc + 1][3] - hi16f(pfh[3]));
#pragma unroll
            for (int dj = 0; dj < 4; dj++) {
                unsigned vf[4];
                ldsm4t(vf, s2u(VH + (tc * 16 + vtrow) * AT_PAD + dj * 16 + vdoff));
                mma16816(oacc[2 * dj], pfh, vf);
                mma16816(oacc[2 * dj + 1], pfh, vf + 2);
                mma16816(oacc[2 * dj], pfl, vf);
                mma16816(oacc[2 * dj + 1], pfl, vf + 2);
                ldsm4t(vf, s2u(VL + (tc * 16 + vtrow) * AT_PAD + dj * 16 + vdoff));
                mma16816(oacc[2 * dj], pfh, vf);
                mma16816(oacc[2 * dj + 1], pfh, vf + 2);
            }
        }
        __syncthreads();
    }

    // epilogue: O/l -> split bf16 for the output GEMM
    float i0 = 1.0f / l0, i1 = 1.0f / l1;
    size_t r0o = ((size_t)b * Ss + sq * 128 + wid * 16 + g) * Aa + h * HDIM;
#pragma unroll
    for (int nd = 0; nd < 8; nd++) {
        int c = nd * 8 + tig * 2;
        float f00 = oacc[nd][0] * i0, f01 = oacc[nd][1] * i0;
        float f10 = oacc[nd][2] * i1, f11 = oacc[nd][3] * i1;
        unsigned h0 = pack2(f00, f01);
        *(unsigned*)(g_oh + r0o + c) = h0;
        *(unsigned*)(g_ol + r0o + c) = pack2(f00 - lo16f(h0), f01 - hi16f(h0));
        unsigned h1 = pack2(f10, f11);
        *(unsigned*)(g_oh + r0o + (size_t)8 * Aa + c) = h1;
        *(unsigned*)(g_ol + r0o + (size_t)8 * Aa + c) = pack2(f10 - lo16f(h1), f11 - hi16f(h1));
    }
}

// ---------------------------------------------------------------------------
// Launch. Inputs: x, y, mask, wq, bq, wk, bk, wv, bv, wo, bo
// ---------------------------------------------------------------------------
extern "C" void kernel_launch(void* const* d_in, const int* in_sizes, int n_in,
                              void* d_out, int out_size) {
    const float* x = (const float*)d_in[0];
    const float* y = (const float*)d_in[1];
    const unsigned char* mask = (const unsigned char*)d_in[2];
    const float* wq = (const float*)d_in[3];
    const float* bq = (const float*)d_in[4];
    const float* wk = (const float*)d_in[5];
    const float* bk = (const float*)d_in[6];
    const float* wv = (const float*)d_in[7];
    const float* bv = (const float*)d_in[8];
    const float* wo = (const float*)d_in[9];
    const float* bo = (const float*)d_in[10];
    float* out = (float*)d_out;

    bf16 *xh, *xl, *yh, *yl, *wqh, *wql, *wkh, *wkl, *wvh, *wvl, *woh, *wol;
    bf16 *qh, *ql, *kh, *kl, *vh, *vl, *oh, *ol;
    cudaGetSymbolAddress((void**)&xh, g_xh);   cudaGetSymbolAddress((void**)&xl, g_xl);
    cudaGetSymbolAddress((void**)&yh, g_yh);   cudaGetSymbolAddress((void**)&yl, g_yl);
    cudaGetSymbolAddress((void**)&wqh, g_wqh); cudaGetSymbolAddress((void**)&wql, g_wql);
    cudaGetSymbolAddress((void**)&wkh, g_wkh); cudaGetSymbolAddress((void**)&wkl, g_wkl);
    cudaGetSymbolAddress((void**)&wvh, g_wvh); cudaGetSymbolAddress((void**)&wvl, g_wvl);
    cudaGetSymbolAddress((void**)&woh, g_woh); cudaGetSymbolAddress((void**)&wol, g_wol);
    cudaGetSymbolAddress((void**)&qh, g_qh);   cudaGetSymbolAddress((void**)&ql, g_ql);
    cudaGetSymbolAddress((void**)&kh, g_kh);   cudaGetSymbolAddress((void**)&kl, g_kl);
    cudaGetSymbolAddress((void**)&vh, g_vh);   cudaGetSymbolAddress((void**)&vl, g_vl);
    cudaGetSymbolAddress((void**)&oh, g_oh);   cudaGetSymbolAddress((void**)&ol, g_ol);

    detect_mask_kernel<<<1, 256>>>(mask);
    convert_mask_kernel<<<(Bb * Tt + 255) / 256, 256>>>(mask);

    const int nact4 = NACT / 4, nwgt4 = NWGT / 4;
    split2_kernel<<<nact4 / 256, 256>>>((const float4*)x, (uint2*)xh, (uint2*)xl, nact4);
    split2_kernel<<<nact4 / 256, 256>>>((const float4*)y, (uint2*)yh, (uint2*)yl, nact4);
    split2_kernel<<<nwgt4 / 256, 256>>>((const float4*)wq, (uint2*)wqh, (uint2*)wql, nwgt4);
    split2_kernel<<<nwgt4 / 256, 256>>>((const float4*)wk, (uint2*)wkh, (uint2*)wkl, nwgt4);
    split2_kernel<<<nwgt4 / 256, 256>>>((const float4*)wv, (uint2*)wvh, (uint2*)wvl, nwgt4);
    split2_kernel<<<nwgt4 / 256, 256>>>((const float4*)wo, (uint2*)woh, (uint2*)wol, nwgt4);

    dim3 gP(Aa / 128, (Bb * Ss) / 128);
    gemm_split<<<gP, 256>>>(xh, xl, wqh, wql, bq, qh, ql, nullptr, Bb * Ss, Aa, Hh);
    gemm_split<<<gP, 256>>>(yh, yl, wkh, wkl, bk, kh, kl, nullptr, Bb * Tt, Aa, Hh);
    gemm_split<<<gP, 256>>>(yh, yl, wvh, wvl, bv, vh, vl, nullptr, Bb * Tt, Aa, Hh);

    cudaFuncSetAttribute(attn_mma, cudaFuncAttributeMaxDynamicSharedMemorySize,
                         ATT_SMEM_BYTES);
    attn_mma<<<dim3(Ss / 128, NHEAD, Bb), 256, ATT_SMEM_BYTES>>>();

    dim3 gO(Hh / 128, (Bb * Ss) / 128);
    gemm_split<<<gO, 256>>>(oh, ol, woh, wol, bo, nullptr, nullptr, out, Bb * Ss, Hh, Aa);
}

// round 12
// speedup vs baseline: 3.3636x; 1.0994x over previous
#include <cuda_runtime.h>
#include <cuda_bf16.h>
#include <math.h>
#include <stdint.h>

// Problem constants
#define Bb 4
#define Ss 2048
#define Tt 2048
#define Hh 1024
#define Aa 1024
#define NHEAD 16
#define HDIM 64

typedef __nv_bfloat16 bf16;

// ---------------------------------------------------------------------------
// Scratch (device globals: allocation-guard-safe). All bf16 split pairs.
// ---------------------------------------------------------------------------
#define NACT (8192 * 1024)
#define NWGT (1024 * 1024)
__device__ bf16 g_xh[NACT], g_xl[NACT];
__device__ bf16 g_yh[NACT], g_yl[NACT];
__device__ bf16 g_wqh[NWGT], g_wql[NWGT];
__device__ bf16 g_wkh[NWGT], g_wkl[NWGT];
__device__ bf16 g_wvh[NWGT], g_wvl[NWGT];
__device__ bf16 g_woh[NWGT], g_wol[NWGT];
__device__ bf16 g_qh[NACT], g_ql[NACT];
__device__ bf16 g_kh[NACT], g_kl[NACT];
__device__ bf16 g_vh[NACT], g_vl[NACT];
__device__ bf16 g_oh[NACT], g_ol[NACT];
__device__ float d_maskf[Bb * Tt];
__device__ int d_maskmode;

// ---------------------------------------------------------------------------
// PTX helpers
// ---------------------------------------------------------------------------
__device__ __forceinline__ unsigned pack2(float lo, float hi) {
    unsigned r;
    asm("cvt.rn.bf16x2.f32 %0, %1, %2;" : "=r"(r) : "f"(hi), "f"(lo));
    return r;
}
__device__ __forceinline__ float lo16f(unsigned u) { return __uint_as_float(u << 16); }
__device__ __forceinline__ float hi16f(unsigned u) { return __uint_as_float(u & 0xFFFF0000u); }

__device__ __forceinline__ void mma16816(float* c, const unsigned* a, const unsigned* b) {
    asm volatile(
        "mma.sync.aligned.m16n8k16.row.col.f32.bf16.bf16.f32 "
        "{%0,%1,%2,%3}, {%4,%5,%6,%7}, {%8,%9}, {%0,%1,%2,%3};\n"
        : "+f"(c[0]), "+f"(c[1]), "+f"(c[2]), "+f"(c[3])
        : "r"(a[0]), "r"(a[1]), "r"(a[2]), "r"(a[3]), "r"(b[0]), "r"(b[1]));
}
__device__ __forceinline__ unsigned s2u(const void* p) {
    return (unsigned)__cvta_generic_to_shared(p);
}
__device__ __forceinline__ void ldsm4(unsigned* r, unsigned addr) {
    asm volatile("ldmatrix.sync.aligned.m8n8.x4.shared.b16 {%0,%1,%2,%3}, [%4];\n"
                 : "=r"(r[0]), "=r"(r[1]), "=r"(r[2]), "=r"(r[3]) : "r"(addr));
}
__device__ __forceinline__ void ldsm4t(unsigned* r, unsigned addr) {
    asm volatile("ldmatrix.sync.aligned.m8n8.x4.trans.shared.b16 {%0,%1,%2,%3}, [%4];\n"
                 : "=r"(r[0]), "=r"(r[1]), "=r"(r[2]), "=r"(r[3]) : "r"(addr));
}
__device__ __forceinline__ void cpasync16(unsigned sdst, const void* gsrc) {
    asm volatile("cp.async.cg.shared.global [%0], [%1], 16;\n" :: "r"(sdst), "l"(gsrc));
}
#define CP_COMMIT asm volatile("cp.async.commit_group;\n")
#define CP_WAIT0 asm volatile("cp.async.wait_group 0;\n")
#define CP_WAIT1 asm volatile("cp.async.wait_group 1;\n")

// ---------------------------------------------------------------------------
// Mask dtype detection (bool8 / int32 / float32) + conversion
// ---------------------------------------------------------------------------
__global__ void detect_mask_kernel(const unsigned char* __restrict__ m) {
    const unsigned int* w = (const unsigned int*)m;
    int okf = 1, oki = 1, anyf = 0;
    for (int i = threadIdx.x; i < 2048; i += blockDim.x) {
        unsigned int v = w[i];
        if (v != 0u && v != 0x3F800000u) okf = 0;
        if (v == 0x3F800000u) anyf = 1;
        if (v > 1u) oki = 0;
    }
    okf = __syncthreads_and(okf);
    anyf = __syncthreads_or(anyf);
    oki = __syncthreads_and(oki);
    if (threadIdx.x == 0) d_maskmode = (okf && anyf) ? 0 : (oki ? 1 : 2);
}

__global__ void convert_mask_kernel(const unsigned char* __restrict__ m) {
    int i = blockIdx.x * blockDim.x + threadIdx.x;
    if (i >= Bb * Tt) return;
    int mode = d_maskmode;
    float v;
    if (mode == 0)      v = ((const float*)m)[i];
    else if (mode == 1) v = (float)((const int*)m)[i];
    else                v = (float)m[i];
    d_maskf[i] = (v != 0.0f) ? 1.0f : 0.0f;
}

// ---------------------------------------------------------------------------
// fp32 -> (hi, lo) bf16 split, vectorized by 4
// ---------------------------------------------------------------------------
__global__ void split2_kernel(const float4* __restrict__ src, uint2* __restrict__ hi,
                              uint2* __restrict__ lo, int n4) {
    int i = blockIdx.x * blockDim.x + threadIdx.x;
    if (i >= n4) return;
    float4 v = src[i];
    unsigned h01 = pack2(v.x, v.y);
    unsigned h23 = pack2(v.z, v.w);
    hi[i] = make_uint2(h01, h23);
    lo[i] = make_uint2(pack2(v.x - lo16f(h01), v.y - hi16f(h01)),
                       pack2(v.z - lo16f(h23), v.w - hi16f(h23)));
}

// ---------------------------------------------------------------------------
// Fused split-precision bf16 tensor-core GEMM (single K-pass, 3 terms/chunk):
// C = (Ah+Al)(Wh+Wl) + bias ~= Ah*Wh + Al*Wh + Ah*Wl
// Block 128x128, BK=32, 8 warps (2x4), warp tile 64x32, mma m16n8k16.
// Dynamic smem, double-buffered cp.async. Output split bf16 or fp32.
// ---------------------------------------------------------------------------
#define GA_ELEMS (128 * 40)     // one A matrix (hi or lo) per stage
#define GW_ELEMS (32 * 136)     // one W matrix per stage
#define GSTAGE (2 * GA_ELEMS + 2 * GW_ELEMS)   // elems per stage: Ah Al Wh Wl
#define GF_SMEM (2 * GSTAGE * (int)sizeof(bf16))

__global__ __launch_bounds__(256, 2)
void gemm_fused(const bf16* __restrict__ Ah, const bf16* __restrict__ Al,
                const bf16* __restrict__ Wh, const bf16* __restrict__ Wl,
                const float* __restrict__ bias,
                bf16* __restrict__ Ch, bf16* __restrict__ Cl,
                float* __restrict__ Cf, int M, int N, int K) {
    extern __shared__ bf16 gsm[];
    const int tid = threadIdx.x;
    const int wid = tid >> 5, lane = tid & 31;
    const int wm = wid >> 2, wn = wid & 3;
    const int g = lane >> 2, tig = lane & 3;
    const int row0 = blockIdx.y * 128, col0 = blockIdx.x * 128;

    float acc[4][4][4];
#pragma unroll
    for (int i = 0; i < 4; i++)
#pragma unroll
        for (int j = 0; j < 4; j++)
#pragma unroll
            for (int k = 0; k < 4; k++) acc[i][j][k] = 0.f;

    // Per-stage smem layout: [AhS | AlS | WhS | WlS]
    auto load_stage = [&](int st, int k0) {
        bf16* AhS = gsm + st * GSTAGE;
        bf16* AlS = AhS + GA_ELEMS;
        bf16* WhS = AlS + GA_ELEMS;
        bf16* WlS = WhS + GW_ELEMS;
#pragma unroll
        for (int l = 0; l < 2; l++) {
            int c = tid + l * 256;          // 0..511
            int ar = c >> 2, ac = (c & 3) * 8;
            const size_t ga = (size_t)(row0 + ar) * K + k0 + ac;
            cpasync16(s2u(&AhS[ar * 40 + ac]), Ah + ga);
            cpasync16(s2u(&AlS[ar * 40 + ac]), Al + ga);
            int wr = c >> 4, wc = (c & 15) * 8;
            const size_t gw = (size_t)(k0 + wr) * N + col0 + wc;
            cpasync16(s2u(&WhS[wr * 136 + wc]), Wh + gw);
            cpasync16(s2u(&WlS[wr * 136 + wc]), Wl + gw);
        }
    };

    load_stage(0, 0);
    CP_COMMIT;

    int stage = 0;
    for (int k0 = 0; k0 < K; k0 += 32) {
        if (k0 + 32 < K) {
            load_stage(stage ^ 1, k0 + 32);
            CP_COMMIT;
            CP_WAIT1;
        } else {
            CP_WAIT0;
        }
        __syncthreads();

        const bf16* AhS = gsm + stage * GSTAGE;
        const bf16* AlS = AhS + GA_ELEMS;
        const bf16* WhS = AlS + GA_ELEMS;
        const bf16* WlS = WhS + GW_ELEMS;

#pragma unroll
        for (int kk = 0; kk < 32; kk += 16) {
            const int arow = wm * 64 + (lane & 15);
            const int aoff = kk + 8 * (lane >> 4);
            const int wrow = kk + (lane & 15);
            const int woff = wn * 32 + 8 * (lane >> 4);

            // hi W fragments
            unsigned wh[2][4];
#pragma unroll
            for (int n2 = 0; n2 < 2; n2++)
                ldsm4t(wh[n2], s2u(&WhS[wrow * 136 + woff + n2 * 16]));
            // hi A fragments + term 1: Ah*Wh
            unsigned ah[4][4];
#pragma unroll
            for (int mf = 0; mf < 4; mf++) {
                ldsm4(ah[mf], s2u(&AhS[(arow + mf * 16) * 40 + aoff]));
#pragma unroll
                for (int nf = 0; nf < 4; nf++)
                    mma16816(acc[mf][nf], ah[mf], &wh[nf >> 1][(nf & 1) * 2]);
            }
            // lo A fragments + term 2: Al*Wh
#pragma unroll
            for (int mf = 0; mf < 4; mf++) {
                unsigned al[4];
                ldsm4(al, s2u(&AlS[(arow + mf * 16) * 40 + aoff]));
#pragma unroll
                for (int nf = 0; nf < 4; nf++)
                    mma16816(acc[mf][nf], al, &wh[nf >> 1][(nf & 1) * 2]);
            }
            // lo W fragments + term 3: Ah*Wl
            unsigned wl[2][4];
#pragma unroll
            for (int n2 = 0; n2 < 2; n2++)
                ldsm4t(wl[n2], s2u(&WlS[wrow * 136 + woff + n2 * 16]));
#pragma unroll
            for (int mf = 0; mf < 4; mf++)
#pragma unroll
                for (int nf = 0; nf < 4; nf++)
                    mma16816(acc[mf][nf], ah[mf], &wl[nf >> 1][(nf & 1) * 2]);
        }
        __syncthreads();
        stage ^= 1;
    }

    // epilogue
#pragma unroll
    for (int mf = 0; mf < 4; mf++) {
        size_t r1 = (size_t)(row0 + wm * 64 + mf * 16 + g);
#pragma unroll
        for (int nf = 0; nf < 4; nf++) {
            int c = col0 + wn * 32 + nf * 8 + tig * 2;
            float2 b2 = *(const float2*)&bias[c];
            float v00 = acc[mf][nf][0] + b2.x, v01 = acc[mf][nf][1] + b2.y;
            float v10 = acc[mf][nf][2] + b2.x, v11 = acc[mf][nf][3] + b2.y;
            if (Cf) {
                *(float2*)&Cf[r1 * N + c] = make_float2(v00, v01);
                *(float2*)&Cf[(r1 + 8) * N + c] = make_float2(v10, v11);
            } else {
                unsigned h0 = pack2(v00, v01);
                *(unsigned*)(Ch + r1 * N + c) = h0;
                *(unsigned*)(Cl + r1 * N + c) = pack2(v00 - lo16f(h0), v01 - hi16f(h0));
                unsigned h1 = pack2(v10, v11);
                *(unsigned*)(Ch + (r1 + 8) * N + c) = h1;
                *(unsigned*)(Cl + (r1 + 8) * N + c) = pack2(v10 - lo16f(h1), v11 - hi16f(h1));
            }
        }
    }
}

// ---------------------------------------------------------------------------
// Flash attention with mma.sync, split-bf16 precision (identical to R5).
// ---------------------------------------------------------------------------
#define AT_PAD 72
#define AT_TILE (64 * AT_PAD)
#define AT_BUF (4 * AT_TILE)
#define ATT_SMEM_BYTES (2 * AT_BUF * 2)

__global__ __launch_bounds__(256)
void attn_mma() {
    extern __shared__ bf16 sm[];
    const int sq = blockIdx.x, h = blockIdx.y, b = blockIdx.z;
    const int tid = threadIdx.x, wid = tid >> 5, lane = tid & 31;
    const int g = lane >> 2, tig = lane & 3;

    unsigned qh[4][4], ql[4][4];
    {
        size_t rbase = ((size_t)b * Ss + sq * 128 + wid * 16) * Aa + h * HDIM;
        size_t o00 = rbase + (size_t)g * Aa + tig * 2;
#pragma unroll
        for (int dc = 0; dc < 4; dc++) {
            size_t o = o00 + dc * 16;
            qh[dc][0] = *(const unsigned*)(g_qh + o);
            qh[dc][1] = *(const unsigned*)(g_qh + o + (size_t)8 * Aa);
            qh[dc][2] = *(const unsigned*)(g_qh + o + 8);
            qh[dc][3] = *(const unsigned*)(g_qh + o + (size_t)8 * Aa + 8);
            ql[dc][0] = *(const unsigned*)(g_ql + o);
            ql[dc][1] = *(const unsigned*)(g_ql + o + (size_t)8 * Aa);
            ql[dc][2] = *(const unsigned*)(g_ql + o + 8);
            ql[dc][3] = *(const unsigned*)(g_ql + o + (size_t)8 * Aa + 8);
        }
    }

    float oacc[8][4];
#pragma unroll
    for (int i = 0; i < 8; i++)
#pragma unroll
        for (int j = 0; j < 4; j++) oacc[i][j] = 0.f;
    float mo0 = -INFINITY, mo1 = -INFINITY, l0 = 0.f, l1 = 0.f;

    auto load_tiles = [&](int it, int bb) {
        const size_t base = ((size_t)b * Tt + it * 64) * Aa + h * HDIM;
#pragma unroll
        for (int l = 0; l < 8; l++) {
            int c = tid + l * 256;
            int mat = c >> 9, r = (c >> 3) & 63, ch = c & 7;
            const bf16* src = (mat == 0 ? g_kh : mat == 1 ? g_kl : mat == 2 ? g_vh : g_vl)
                              + base + (size_t)r * Aa + ch * 8;
            cpasync16(s2u(sm + bb * AT_BUF + mat * AT_TILE + r * AT_PAD + ch * 8), src);
        }
    };

    load_tiles(0, 0);
    CP_COMMIT;
    const int NIT = Tt / 64;

#pragma unroll 1
    for (int it = 0; it < NIT; it++) {
        int bb = it & 1;
        if (it + 1 < NIT) { load_tiles(it + 1, bb ^ 1); CP_COMMIT; CP_WAIT1; }
        else               { CP_WAIT0; }
        __syncthreads();

        const bf16* KH = sm + bb * AT_BUF;
        const bf16* KL = KH + AT_TILE;
        const bf16* VH = KH + 2 * AT_TILE;
        const bf16* VL = KH + 3 * AT_TILE;

        float s[8][4];
#pragma unroll
        for (int i = 0; i < 8; i++)
#pragma unroll
            for (int j = 0; j < 4; j++) s[i][j] = 0.f;

        const int ktrow = ((lane >> 4) & 1) * 8 + (lane & 7);
        const int kdoff = ((lane >> 3) & 1) * 8;
#pragma unroll
        for (int dc = 0; dc < 4; dc++) {
#pragma unroll
            for (int j = 0; j < 4; j++) {
                unsigned kf[4];
                ldsm4(kf, s2u(KH + (j * 16 + ktrow) * AT_PAD + dc * 16 + kdoff));
                mma16816(s[2 * j], qh[dc], kf);
                mma16816(s[2 * j + 1], qh[dc], kf + 2);
                mma16816(s[2 * j], ql[dc], kf);
                mma16816(s[2 * j + 1], ql[dc], kf + 2);
            }
        }
#pragma unroll
        for (int dc = 0; dc < 4; dc++) {
#pragma unroll
            for (int j = 0; j < 4; j++) {
                unsigned kf[4];
                ldsm4(kf, s2u(KL + (j * 16 + ktrow) * AT_PAD + dc * 16 + kdoff));
                mma16816(s[2 * j], qh[dc], kf);
                mma16816(s[2 * j + 1], qh[dc], kf + 2);
            }
        }

        const float* mrow = d_maskf + b * Tt + it * 64;
        float mt0 = -INFINITY, mt1 = -INFINITY;
#pragma unroll
        for (int n = 0; n < 8; n++) {
            float2 m2 = *(const float2*)&mrow[n * 8 + tig * 2];
            s[n][0] = (m2.x != 0.f) ? s[n][0] * 0.125f : -100000.0f;
            s[n][1] = (m2.y != 0.f) ? s[n][1] * 0.125f : -100000.0f;
            s[n][2] = (m2.x != 0.f) ? s[n][2] * 0.125f : -100000.0f;
            s[n][3] = (m2.y != 0.f) ? s[n][3] * 0.125f : -100000.0f;
            mt0 = fmaxf(mt0, fmaxf(s[n][0], s[n][1]));
            mt1 = fmaxf(mt1, fmaxf(s[n][2], s[n][3]));
        }
        mt0 = fmaxf(mt0, __shfl_xor_sync(0xFFFFFFFFu, mt0, 1));
        mt0 = fmaxf(mt0, __shfl_xor_sync(0xFFFFFFFFu, mt0, 2));
        mt1 = fmaxf(mt1, __shfl_xor_sync(0xFFFFFFFFu, mt1, 1));
        mt1 = fmaxf(mt1, __shfl_xor_sync(0xFFFFFFFFu, mt1, 2));
        float mn0 = fmaxf(mo0, mt0), mn1 = fmaxf(mo1, mt1);
        float a0 = __expf(mo0 - mn0), a1 = __expf(mo1 - mn1);
        float ls0 = 0.f, ls1 = 0.f;
#pragma unroll
        for (int n = 0; n < 8; n++) {
            s[n][0] = __expf(s[n][0] - mn0);
            s[n][1] = __expf(s[n][1] - mn0);
            s[n][2] = __expf(s[n][2] - mn1);
            s[n][3] = __expf(s[n][3] - mn1);
            ls0 += s[n][0] + s[n][1];
            ls1 += s[n][2] + s[n][3];
        }
        ls0 += __shfl_xor_sync(0xFFFFFFFFu, ls0, 1);
        ls0 += __shfl_xor_sync(0xFFFFFFFFu, ls0, 2);
        ls1 += __shfl_xor_sync(0xFFFFFFFFu, ls1, 1);
        ls1 += __shfl_xor_sync(0xFFFFFFFFu, ls1, 2);
        l0 = l0 * a0 + ls0;
        l1 = l1 * a1 + ls1;
#pragma unroll
        for (int nd = 0; nd < 8; nd++) {
            oacc[nd][0] *= a0; oacc[nd][1] *= a0;
            oacc[nd][2] *= a1; oacc[nd][3] *= a1;
        }
        mo0 = mn0; mo1 = mn1;

        const int vtrow = lane & 15;
        const int vdoff = (lane >> 4) * 8;
#pragma unroll
        for (int tc = 0; tc < 4; tc++) {
            unsigned pfh[4], pfl[4];
            pfh[0] = pack2(s[2 * tc][0], s[2 * tc][1]);
            pfh[1] = pack2(s[2 * tc][2], s[2 * tc][3]);
            pfh[2] = pack2(s[2 * tc + 1][0], s[2 * tc + 1][1]);
            pfh[3] = pack2(s[2 * tc + 1][2], s[2 * tc + 1][3]);
            pfl[0] = pack2(s[2 * tc][0] - lo16f(pfh[0]), s[2 * tc][1] - hi16f(pfh[0]));
            pfl[1] = pack2(s[2 * tc][2] - lo16f(pfh[1]), s[2 * tc][3] - hi16f(pfh[1]));
            pfl[2] = pack2(s[2 * tc + 1][0] - lo16f(pfh[2]), s[2 * tc + 1][1] - hi16f(pfh[2]));
            pfl[3] = pack2(s[2 * tc + 1][2] - lo16f(pfh[3]), s[2 * tc + 1][3] - hi16f(pfh[3]));
#pragma unroll
            for (int dj = 0; dj < 4; dj++) {
                unsigned vf[4];
                ldsm4t(vf, s2u(VH + (tc * 16 + vtrow) * AT_PAD + dj * 16 + vdoff));
                mma16816(oacc[2 * dj], pfh, vf);
                mma16816(oacc[2 * dj + 1], pfh, vf + 2);
                mma16816(oacc[2 * dj], pfl, vf);
                mma16816(oacc[2 * dj + 1], pfl, vf + 2);
                ldsm4t(vf, s2u(VL + (tc * 16 + vtrow) * AT_PAD + dj * 16 + vdoff));
                mma16816(oacc[2 * dj], pfh, vf);
                mma16816(oacc[2 * dj + 1], pfh, vf + 2);
            }
        }
        __syncthreads();
    }

    float i0 = 1.0f / l0, i1 = 1.0f / l1;
    size_t r0o = ((size_t)b * Ss + sq * 128 + wid * 16 + g) * Aa + h * HDIM;
#pragma unroll
    for (int nd = 0; nd < 8; nd++) {
        int c = nd * 8 + tig * 2;
        float f00 = oacc[nd][0] * i0, f01 = oacc[nd][1] * i0;
        float f10 = oacc[nd][2] * i1, f11 = oacc[nd][3] * i1;
        unsigned h0 = pack2(f00, f01);
        *(unsigned*)(g_oh + r0o + c) = h0;
        *(unsigned*)(g_ol + r0o + c) = pack2(f00 - lo16f(h0), f01 - hi16f(h0));
        unsigned h1 = pack2(f10, f11);
        *(unsigned*)(g_oh + r0o + (size_t)8 * Aa + c) = h1;
        *(unsigned*)(g_ol + r0o + (size_t)8 * Aa + c) = pack2(f10 - lo16f(h1), f11 - hi16f(h1));
    }
}

// ---------------------------------------------------------------------------
// Launch. Inputs: x, y, mask, wq, bq, wk, bk, wv, bv, wo, bo
// ---------------------------------------------------------------------------
extern "C" void kernel_launch(void* const* d_in, const int* in_sizes, int n_in,
                              void* d_out, int out_size) {
    const float* x = (const float*)d_in[0];
    const float* y = (const float*)d_in[1];
    const unsigned char* mask = (const unsigned char*)d_in[2];
    const float* wq = (const float*)d_in[3];
    const float* bq = (const float*)d_in[4];
    const float* wk = (const float*)d_in[5];
    const float* bk = (const float*)d_in[6];
    const float* wv = (const float*)d_in[7];
    const float* bv = (const float*)d_in[8];
    const float* wo = (const float*)d_in[9];
    const float* bo = (const float*)d_in[10];
    float* out = (float*)d_out;

    bf16 *xh, *xl, *yh, *yl, *wqh, *wql, *wkh, *wkl, *wvh, *wvl, *woh, *wol;
    bf16 *qh, *ql, *kh, *kl, *vh, *vl, *oh, *ol;
    cudaGetSymbolAddress((void**)&xh, g_xh);   cudaGetSymbolAddress((void**)&xl, g_xl);
    cudaGetSymbolAddress((void**)&yh, g_yh);   cudaGetSymbolAddress((void**)&yl, g_yl);
    cudaGetSymbolAddress((void**)&wqh, g_wqh); cudaGetSymbolAddress((void**)&wql, g_wql);
    cudaGetSymbolAddress((void**)&wkh, g_wkh); cudaGetSymbolAddress((void**)&wkl, g_wkl);
    cudaGetSymbolAddress((void**)&wvh, g_wvh); cudaGetSymbolAddress((void**)&wvl, g_wvl);
    cudaGetSymbolAddress((void**)&woh, g_woh); cudaGetSymbolAddress((void**)&wol, g_wol);
    cudaGetSymbolAddress((void**)&qh, g_qh);   cudaGetSymbolAddress((void**)&ql, g_ql);
    cudaGetSymbolAddress((void**)&kh, g_kh);   cudaGetSymbolAddress((void**)&kl, g_kl);
    cudaGetSymbolAddress((void**)&vh, g_vh);   cudaGetSymbolAddress((void**)&vl, g_vl);
    cudaGetSymbolAddress((void**)&oh, g_oh);   cudaGetSymbolAddress((void**)&ol, g_ol);

    detect_mask_kernel<<<1, 256>>>(mask);
    convert_mask_kernel<<<(Bb * Tt + 255) / 256, 256>>>(mask);

    const int nact4 = NACT / 4, nwgt4 = NWGT / 4;
    split2_kernel<<<nact4 / 256, 256>>>((const float4*)x, (uint2*)xh, (uint2*)xl, nact4);
    split2_kernel<<<nact4 / 256, 256>>>((const float4*)y, (uint2*)yh, (uint2*)yl, nact4);
    split2_kernel<<<nwgt4 / 256, 256>>>((const float4*)wq, (uint2*)wqh, (uint2*)wql, nwgt4);
    split2_kernel<<<nwgt4 / 256, 256>>>((const float4*)wk, (uint2*)wkh, (uint2*)wkl, nwgt4);
    split2_kernel<<<nwgt4 / 256, 256>>>((const float4*)wv, (uint2*)wvh, (uint2*)wvl, nwgt4);
    split2_kernel<<<nwgt4 / 256, 256>>>((const float4*)wo, (uint2*)woh, (uint2*)wol, nwgt4);

    cudaFuncSetAttribute(gemm_fused, cudaFuncAttributeMaxDynamicSharedMemorySize, GF_SMEM);

    dim3 gP(Aa / 128, (Bb * Ss) / 128);
    gemm_fused<<<gP, 256, GF_SMEM>>>(xh, xl, wqh, wql, bq, qh, ql, nullptr, Bb * Ss, Aa, Hh);
    gemm_fused<<<gP, 256, GF_SMEM>>>(yh, yl, wkh, wkl, bk, kh, kl, nullptr, Bb * Tt, Aa, Hh);
    gemm_fused<<<gP, 256, GF_SMEM>>>(yh, yl, wvh, wvl, bv, vh, vl, nullptr, Bb * Tt, Aa, Hh);

    cudaFuncSetAttribute(attn_mma, cudaFuncAttributeMaxDynamicSharedMemorySize,
                         ATT_SMEM_BYTES);
    attn_mma<<<dim3(Ss / 128, NHEAD, Bb), 256, ATT_SMEM_BYTES>>>();

    dim3 gO(Hh / 128, (Bb * Ss) / 128);
    gemm_fused<<<gO, 256, GF_SMEM>>>(oh, ol, woh, wol, bo, nullptr, nullptr, out, Bb * Ss, Hh, Aa);
}

// round 15
// speedup vs baseline: 4.8702x; 1.4479x over previous
#include <cuda_runtime.h>
#include <cuda_bf16.h>
#include <cuda_fp16.h>
#include <math.h>
#include <stdint.h>

// Problem constants
#define Bb 4
#define Ss 2048
#define Tt 2048
#define Hh 1024
#define Aa 1024
#define NHEAD 16
#define HDIM 64

typedef __nv_bfloat16 bf16;

// ---------------------------------------------------------------------------
// Scratch (device globals). Activations/weights: bf16 split pairs (GEMM).
// q/k/v: plain fp16. O: bf16 split (feeds output GEMM).
// ---------------------------------------------------------------------------
#define NACT (8192 * 1024)
#define NWGT (1024 * 1024)
__device__ bf16 g_xh[NACT], g_xl[NACT];
__device__ bf16 g_yh[NACT], g_yl[NACT];
__device__ bf16 g_wqh[NWGT], g_wql[NWGT];
__device__ bf16 g_wkh[NWGT], g_wkl[NWGT];
__device__ bf16 g_wvh[NWGT], g_wvl[NWGT];
__device__ bf16 g_woh[NWGT], g_wol[NWGT];
__device__ __half g_q16[NACT];
__device__ __half g_k16[NACT];
__device__ __half g_v16[NACT];
__device__ bf16 g_oh[NACT], g_ol[NACT];
__device__ float d_maskf[Bb * Tt];
__device__ int d_maskmode;

// ---------------------------------------------------------------------------
// PTX helpers
// ---------------------------------------------------------------------------
__device__ __forceinline__ unsigned pack2(float lo, float hi) {
    unsigned r;
    asm("cvt.rn.bf16x2.f32 %0, %1, %2;" : "=r"(r) : "f"(hi), "f"(lo));
    return r;
}
__device__ __forceinline__ unsigned pack2h(float lo, float hi) {
    unsigned r;
    asm("cvt.rn.f16x2.f32 %0, %1, %2;" : "=r"(r) : "f"(hi), "f"(lo));
    return r;
}
__device__ __forceinline__ float lo16f(unsigned u) { return __uint_as_float(u << 16); }
__device__ __forceinline__ float hi16f(unsigned u) { return __uint_as_float(u & 0xFFFF0000u); }

__device__ __forceinline__ void mma16816(float* c, const unsigned* a, const unsigned* b) {
    asm volatile(
        "mma.sync.aligned.m16n8k16.row.col.f32.bf16.bf16.f32 "
        "{%0,%1,%2,%3}, {%4,%5,%6,%7}, {%8,%9}, {%0,%1,%2,%3};\n"
        : "+f"(c[0]), "+f"(c[1]), "+f"(c[2]), "+f"(c[3])
        : "r"(a[0]), "r"(a[1]), "r"(a[2]), "r"(a[3]), "r"(b[0]), "r"(b[1]));
}
__device__ __forceinline__ void mma16816h(float* c, const unsigned* a, const unsigned* b) {
    asm volatile(
        "mma.sync.aligned.m16n8k16.row.col.f32.f16.f16.f32 "
        "{%0,%1,%2,%3}, {%4,%5,%6,%7}, {%8,%9}, {%0,%1,%2,%3};\n"
        : "+f"(c[0]), "+f"(c[1]), "+f"(c[2]), "+f"(c[3])
        : "r"(a[0]), "r"(a[1]), "r"(a[2]), "r"(a[3]), "r"(b[0]), "r"(b[1]));
}
__device__ __forceinline__ unsigned s2u(const void* p) {
    return (unsigned)__cvta_generic_to_shared(p);
}
__device__ __forceinline__ void ldsm4(unsigned* r, unsigned addr) {
    asm volatile("ldmatrix.sync.aligned.m8n8.x4.shared.b16 {%0,%1,%2,%3}, [%4];\n"
                 : "=r"(r[0]), "=r"(r[1]), "=r"(r[2]), "=r"(r[3]) : "r"(addr));
}
__device__ __forceinline__ void ldsm4t(unsigned* r, unsigned addr) {
    asm volatile("ldmatrix.sync.aligned.m8n8.x4.trans.shared.b16 {%0,%1,%2,%3}, [%4];\n"
                 : "=r"(r[0]), "=r"(r[1]), "=r"(r[2]), "=r"(r[3]) : "r"(addr));
}
__device__ __forceinline__ void cpasync16(unsigned sdst, const void* gsrc) {
    asm volatile("cp.async.cg.shared.global [%0], [%1], 16;\n" :: "r"(sdst), "l"(gsrc));
}
#define CP_COMMIT asm volatile("cp.async.commit_group;\n")
#define CP_WAIT0 asm volatile("cp.async.wait_group 0;\n")
#define CP_WAIT1 asm volatile("cp.async.wait_group 1;\n")

// ---------------------------------------------------------------------------
// Mask dtype detection (bool8 / int32 / float32) + conversion
// ---------------------------------------------------------------------------
__global__ void detect_mask_kernel(const unsigned char* __restrict__ m) {
    const unsigned int* w = (const unsigned int*)m;
    int okf = 1, oki = 1, anyf = 0;
    for (int i = threadIdx.x; i < 2048; i += blockDim.x) {
        unsigned int v = w[i];
        if (v != 0u && v != 0x3F800000u) okf = 0;
        if (v == 0x3F800000u) anyf = 1;
        if (v > 1u) oki = 0;
    }
    okf = __syncthreads_and(okf);
    anyf = __syncthreads_or(anyf);
    oki = __syncthreads_and(oki);
    if (threadIdx.x == 0) d_maskmode = (okf && anyf) ? 0 : (oki ? 1 : 2);
}

__global__ void convert_mask_kernel(const unsigned char* __restrict__ m) {
    int i = blockIdx.x * blockDim.x + threadIdx.x;
    if (i >= Bb * Tt) return;
    int mode = d_maskmode;
    float v;
    if (mode == 0)      v = ((const float*)m)[i];
    else if (mode == 1) v = (float)((const int*)m)[i];
    else                v = (float)m[i];
    d_maskf[i] = (v != 0.0f) ? 1.0f : 0.0f;
}

// ---------------------------------------------------------------------------
// fp32 -> (hi, lo) bf16 split. Fused over multiple tensors via blockIdx.z.
// ---------------------------------------------------------------------------
__device__ __forceinline__ void split_body(const float4* src, uint2* hi, uint2* lo,
                                           int i) {
    float4 v = src[i];
    unsigned h01 = pack2(v.x, v.y);
    unsigned h23 = pack2(v.z, v.w);
    hi[i] = make_uint2(h01, h23);
    lo[i] = make_uint2(pack2(v.x - lo16f(h01), v.y - hi16f(h01)),
                       pack2(v.z - lo16f(h23), v.w - hi16f(h23)));
}

__global__ void splitact_kernel(const float4* __restrict__ x, const float4* __restrict__ y) {
    int i = blockIdx.x * blockDim.x + threadIdx.x;
    if (blockIdx.z == 0) split_body(x, (uint2*)g_xh, (uint2*)g_xl, i);
    else                 split_body(y, (uint2*)g_yh, (uint2*)g_yl, i);
}

__global__ void splitw_kernel(const float4* __restrict__ wq, const float4* __restrict__ wk,
                              const float4* __restrict__ wv, const float4* __restrict__ wo) {
    int i = blockIdx.x * blockDim.x + threadIdx.x;
    switch (blockIdx.z) {
        case 0: split_body(wq, (uint2*)g_wqh, (uint2*)g_wql, i); break;
        case 1: split_body(wk, (uint2*)g_wkh, (uint2*)g_wkl, i); break;
        case 2: split_body(wv, (uint2*)g_wvh, (uint2*)g_wvl, i); break;
        default: split_body(wo, (uint2*)g_woh, (uint2*)g_wol, i); break;
    }
}

// ---------------------------------------------------------------------------
// Fused split-precision bf16 tensor-core GEMM core (single K-pass, 3 terms):
// C = (Ah+Al)(Wh+Wl) + bias ~= Ah*Wh + Al*Wh + Ah*Wl
// Block 128x128, BK=32, 8 warps, warp tile 64x32.
// Output: fp16 (C16) if non-null, else fp32 (Cf).
// ---------------------------------------------------------------------------
#define GA_ELEMS (128 * 40)
#define GW_ELEMS (32 * 136)
#define GSTAGE (2 * GA_ELEMS + 2 * GW_ELEMS)
#define GF_SMEM (2 * GSTAGE * (int)sizeof(bf16))

__device__ __forceinline__ void gemm_core(
        const bf16* __restrict__ Ah, const bf16* __restrict__ Al,
        const bf16* __restrict__ Wh, const bf16* __restrict__ Wl,
        const float* __restrict__ bias, __half* __restrict__ C16,
        float* __restrict__ Cf, int M, int N, int K, bf16* gsm) {
    const int tid = threadIdx.x;
    const int wid = tid >> 5, lane = tid & 31;
    const int wm = wid >> 2, wn = wid & 3;
    const int g = lane >> 2, tig = lane & 3;
    const int row0 = blockIdx.y * 128, col0 = blockIdx.x * 128;

    float acc[4][4][4];
#pragma unroll
    for (int i = 0; i < 4; i++)
#pragma unroll
        for (int j = 0; j < 4; j++)
#pragma unroll
            for (int k = 0; k < 4; k++) acc[i][j][k] = 0.f;

    auto load_stage = [&](int st, int k0) {
        bf16* AhS = gsm + st * GSTAGE;
        bf16* AlS = AhS + GA_ELEMS;
        bf16* WhS = AlS + GA_ELEMS;
        bf16* WlS = WhS + GW_ELEMS;
#pragma unroll
        for (int l = 0; l < 2; l++) {
            int c = tid + l * 256;
            int ar = c >> 2, ac = (c & 3) * 8;
            const size_t ga = (size_t)(row0 + ar) * K + k0 + ac;
            cpasync16(s2u(&AhS[ar * 40 + ac]), Ah + ga);
            cpasync16(s2u(&AlS[ar * 40 + ac]), Al + ga);
            int wr = c >> 4, wc = (c & 15) * 8;
            const size_t gw = (size_t)(k0 + wr) * N + col0 + wc;
            cpasync16(s2u(&WhS[wr * 136 + wc]), Wh + gw);
            cpasync16(s2u(&WlS[wr * 136 + wc]), Wl + gw);
        }
    };

    load_stage(0, 0);
    CP_COMMIT;

    int stage = 0;
    for (int k0 = 0; k0 < K; k0 += 32) {
        if (k0 + 32 < K) {
            load_stage(stage ^ 1, k0 + 32);
            CP_COMMIT;
            CP_WAIT1;
        } else {
            CP_WAIT0;
        }
        __syncthreads();

        const bf16* AhS = gsm + stage * GSTAGE;
        const bf16* AlS = AhS + GA_ELEMS;
        const bf16* WhS = AlS + GA_ELEMS;
        const bf16* WlS = WhS + GW_ELEMS;

#pragma unroll
        for (int kk = 0; kk < 32; kk += 16) {
            const int arow = wm * 64 + (lane & 15);
            const int aoff = kk + 8 * (lane >> 4);
            const int wrow = kk + (lane & 15);
            const int woff = wn * 32 + 8 * (lane >> 4);

            unsigned wh[2][4];
#pragma unroll
            for (int n2 = 0; n2 < 2; n2++)
                ldsm4t(wh[n2], s2u(&WhS[wrow * 136 + woff + n2 * 16]));
            unsigned ah[4][4];
#pragma unroll
            for (int mf = 0; mf < 4; mf++) {
                ldsm4(ah[mf], s2u(&AhS[(arow + mf * 16) * 40 + aoff]));
#pragma unroll
                for (int nf = 0; nf < 4; nf++)
                    mma16816(acc[mf][nf], ah[mf], &wh[nf >> 1][(nf & 1) * 2]);
            }
#pragma unroll
            for (int mf = 0; mf < 4; mf++) {
                unsigned al[4];
                ldsm4(al, s2u(&AlS[(arow + mf * 16) * 40 + aoff]));
#pragma unroll
                for (int nf = 0; nf < 4; nf++)
                    mma16816(acc[mf][nf], al, &wh[nf >> 1][(nf & 1) * 2]);
            }
            unsigned wl[2][4];
#pragma unroll
            for (int n2 = 0; n2 < 2; n2++)
                ldsm4t(wl[n2], s2u(&WlS[wrow * 136 + woff + n2 * 16]));
#pragma unroll
            for (int mf = 0; mf < 4; mf++)
#pragma unroll
                for (int nf = 0; nf < 4; nf++)
                    mma16816(acc[mf][nf], ah[mf], &wl[nf >> 1][(nf & 1) * 2]);
        }
        __syncthreads();
        stage ^= 1;
    }

#pragma unroll
    for (int mf = 0; mf < 4; mf++) {
        size_t r1 = (size_t)(row0 + wm * 64 + mf * 16 + g);
#pragma unroll
        for (int nf = 0; nf < 4; nf++) {
            int c = col0 + wn * 32 + nf * 8 + tig * 2;
            float2 b2 = *(const float2*)&bias[c];
            float v00 = acc[mf][nf][0] + b2.x, v01 = acc[mf][nf][1] + b2.y;
            float v10 = acc[mf][nf][2] + b2.x, v11 = acc[mf][nf][3] + b2.y;
            if (C16) {
                *(unsigned*)(C16 + r1 * N + c) = pack2h(v00, v01);
                *(unsigned*)(C16 + (r1 + 8) * N + c) = pack2h(v10, v11);
            } else {
                *(float2*)&Cf[r1 * N + c] = make_float2(v00, v01);
                *(float2*)&Cf[(r1 + 8) * N + c] = make_float2(v10, v11);
            }
        }
    }
}

// QKV fused: blockIdx.z selects projection. M=8192, N=K=1024.
__global__ __launch_bounds__(256, 2)
void gemm_qkv(const float* __restrict__ bq, const float* __restrict__ bk,
              const float* __restrict__ bv) {
    extern __shared__ bf16 gsm[];
    const bf16 *Ah, *Al, *Wh, *Wl;
    const float* bias;
    __half* C16;
    if (blockIdx.z == 0) { Ah = g_xh; Al = g_xl; Wh = g_wqh; Wl = g_wql; bias = bq; C16 = g_q16; }
    else if (blockIdx.z == 1) { Ah = g_yh; Al = g_yl; Wh = g_wkh; Wl = g_wkl; bias = bk; C16 = g_k16; }
    else { Ah = g_yh; Al = g_yl; Wh = g_wvh; Wl = g_wvl; bias = bv; C16 = g_v16; }
    gemm_core(Ah, Al, Wh, Wl, bias, C16, nullptr, Bb * Ss, Aa, Hh, gsm);
}

__global__ __launch_bounds__(256, 2)
void gemm_out(const float* __restrict__ bo, float* __restrict__ out) {
    extern __shared__ bf16 gsm[];
    gemm_core(g_oh, g_ol, g_woh, g_wol, bo, nullptr, out, Bb * Ss, Hh, Aa, gsm);
}

// ---------------------------------------------------------------------------
// Flash attention, pure fp16 operands (fp32 accum + fp32 softmax).
// Block: 128 q-rows, 8 warps (16 rows each, full t=64 -> warp-local softmax).
// Double-buffered cp.async K/V fp16 tiles.
// ---------------------------------------------------------------------------
#define AT_PAD 72
#define AT_TILE (64 * AT_PAD)           // halves per matrix
#define AT_BUF (2 * AT_TILE)            // K, V
#define ATT_SMEM_BYTES (2 * AT_BUF * 2) // 36864 B

__global__ __launch_bounds__(256)
void attn_mma16() {
    extern __shared__ __half smh[];
    const int sq = blockIdx.x, h = blockIdx.y, b = blockIdx.z;
    const int tid = threadIdx.x, wid = tid >> 5, lane = tid & 31;
    const int g = lane >> 2, tig = lane & 3;

    // Q fragments (fp16), 4 d-chunks of 16
    unsigned qf[4][4];
    {
        size_t rbase = ((size_t)b * Ss + sq * 128 + wid * 16) * Aa + h * HDIM;
        size_t o00 = rbase + (size_t)g * Aa + tig * 2;
#pragma unroll
        for (int dc = 0; dc < 4; dc++) {
            size_t o = o00 + dc * 16;
            qf[dc][0] = *(const unsigned*)(g_q16 + o);
            qf[dc][1] = *(const unsigned*)(g_q16 + o + (size_t)8 * Aa);
            qf[dc][2] = *(const unsigned*)(g_q16 + o + 8);
            qf[dc][3] = *(const unsigned*)(g_q16 + o + (size_t)8 * Aa + 8);
        }
    }

    float oacc[8][4];
#pragma unroll
    for (int i = 0; i < 8; i++)
#pragma unroll
        for (int j = 0; j < 4; j++) oacc[i][j] = 0.f;
    float mo0 = -INFINITY, mo1 = -INFINITY, l0 = 0.f, l1 = 0.f;

    auto load_tiles = [&](int it, int bb) {
        const size_t base = ((size_t)b * Tt + it * 64) * Aa + h * HDIM;
#pragma unroll
        for (int l = 0; l < 4; l++) {
            int c = tid + l * 256;            // 0..1023
            int mat = c >> 9, r = (c >> 3) & 63, ch = c & 7;
            const __half* src = (mat == 0 ? g_k16 : g_v16) + base + (size_t)r * Aa + ch * 8;
            cpasync16(s2u(smh + bb * AT_BUF + mat * AT_TILE + r * AT_PAD + ch * 8), src);
        }
    };

    load_tiles(0, 0);
    CP_COMMIT;
    const int NIT = Tt / 64;

#pragma unroll 1
    for (int it = 0; it < NIT; it++) {
        int bb = it & 1;
        if (it + 1 < NIT) { load_tiles(it + 1, bb ^ 1); CP_COMMIT; CP_WAIT1; }
        else               { CP_WAIT0; }
        __syncthreads();

        const __half* KS = smh + bb * AT_BUF;
        const __half* VS = KS + AT_TILE;

        // ---- S = Q K^T (fp16 x fp16 -> fp32) ----
        float s[8][4];
#pragma unroll
        for (int i = 0; i < 8; i++)
#pragma unroll
            for (int j = 0; j < 4; j++) s[i][j] = 0.f;

        const int ktrow = ((lane >> 4) & 1) * 8 + (lane & 7);
        const int kdoff = ((lane >> 3) & 1) * 8;
#pragma unroll
        for (int dc = 0; dc < 4; dc++) {
#pragma unroll
            for (int j = 0; j < 4; j++) {
                unsigned kf[4];
                ldsm4(kf, s2u(KS + (j * 16 + ktrow) * AT_PAD + dc * 16 + kdoff));
                mma16816h(s[2 * j], qf[dc], kf);
                mma16816h(s[2 * j + 1], qf[dc], kf + 2);
            }
        }

        // ---- scale + mask + online softmax ----
        const float* mrow = d_maskf + b * Tt + it * 64;
        float mt0 = -INFINITY, mt1 = -INFINITY;
#pragma unroll
        for (int n = 0; n < 8; n++) {
            float2 m2 = *(const float2*)&mrow[n * 8 + tig * 2];
            s[n][0] = (m2.x != 0.f) ? s[n][0] * 0.125f : -100000.0f;
            s[n][1] = (m2.y != 0.f) ? s[n][1] * 0.125f : -100000.0f;
            s[n][2] = (m2.x != 0.f) ? s[n][2] * 0.125f : -100000.0f;
            s[n][3] = (m2.y != 0.f) ? s[n][3] * 0.125f : -100000.0f;
            mt0 = fmaxf(mt0, fmaxf(s[n][0], s[n][1]));
            mt1 = fmaxf(mt1, fmaxf(s[n][2], s[n][3]));
        }
        mt0 = fmaxf(mt0, __shfl_xor_sync(0xFFFFFFFFu, mt0, 1));
        mt0 = fmaxf(mt0, __shfl_xor_sync(0xFFFFFFFFu, mt0, 2));
        mt1 = fmaxf(mt1, __shfl_xor_sync(0xFFFFFFFFu, mt1, 1));
        mt1 = fmaxf(mt1, __shfl_xor_sync(0xFFFFFFFFu, mt1, 2));
        float mn0 = fmaxf(mo0, mt0), mn1 = fmaxf(mo1, mt1);
        float a0 = __expf(mo0 - mn0), a1 = __expf(mo1 - mn1);
        float ls0 = 0.f, ls1 = 0.f;
#pragma unroll
        for (int n = 0; n < 8; n++) {
            s[n][0] = __expf(s[n][0] - mn0);
            s[n][1] = __expf(s[n][1] - mn0);
            s[n][2] = __expf(s[n][2] - mn1);
            s[n][3] = __expf(s[n][3] - mn1);
            ls0 += s[n][0] + s[n][1];
            ls1 += s[n][2] + s[n][3];
        }
        ls0 += __shfl_xor_sync(0xFFFFFFFFu, ls0, 1);
        ls0 += __shfl_xor_sync(0xFFFFFFFFu, ls0, 2);
        ls1 += __shfl_xor_sync(0xFFFFFFFFu, ls1, 1);
        ls1 += __shfl_xor_sync(0xFFFFFFFFu, ls1, 2);
        l0 = l0 * a0 + ls0;
        l1 = l1 * a1 + ls1;
#pragma unroll
        for (int nd = 0; nd < 8; nd++) {
            oacc[nd][0] *= a0; oacc[nd][1] *= a0;
            oacc[nd][2] *= a1; oacc[nd][3] *= a1;
        }
        mo0 = mn0; mo1 = mn1;

        // ---- O += P V (P fp16, V fp16) ----
        const int vtrow = lane & 15;
        const int vdoff = (lane >> 4) * 8;
#pragma unroll
        for (int tc = 0; tc < 4; tc++) {
            unsigned pf[4];
            pf[0] = pack2h(s[2 * tc][0], s[2 * tc][1]);
            pf[1] = pack2h(s[2 * tc][2], s[2 * tc][3]);
            pf[2] = pack2h(s[2 * tc + 1][0], s[2 * tc + 1][1]);
            pf[3] = pack2h(s[2 * tc + 1][2], s[2 * tc + 1][3]);
#pragma unroll
            for (int dj = 0; dj < 4; dj++) {
                unsigned vf[4];
                ldsm4t(vf, s2u(VS + (tc * 16 + vtrow) * AT_PAD + dj * 16 + vdoff));
                mma16816h(oacc[2 * dj], pf, vf);
                mma16816h(oacc[2 * dj + 1], pf, vf + 2);
            }
        }
        __syncthreads();
    }

    // epilogue: O/l -> split bf16 for the output GEMM
    float i0 = 1.0f / l0, i1 = 1.0f / l1;
    size_t r0o = ((size_t)b * Ss + sq * 128 + wid * 16 + g) * Aa + h * HDIM;
#pragma unroll
    for (int nd = 0; nd < 8; nd++) {
        int c = nd * 8 + tig * 2;
        float f00 = oacc[nd][0] * i0, f01 = oacc[nd][1] * i0;
        float f10 = oacc[nd][2] * i1, f11 = oacc[nd][3] * i1;
        unsigned h0 = pack2(f00, f01);
        *(unsigned*)(g_oh + r0o + c) = h0;
        *(unsigned*)(g_ol + r0o + c) = pack2(f00 - lo16f(h0), f01 - hi16f(h0));
        unsigned h1 = pack2(f10, f11);
        *(unsigned*)(g_oh + r0o + (size_t)8 * Aa + c) = h1;
        *(unsigned*)(g_ol + r0o + (size_t)8 * Aa + c) = pack2(f10 - lo16f(h1), f11 - hi16f(h1));
    }
}

// ---------------------------------------------------------------------------
// Launch. Inputs: x, y, mask, wq, bq, wk, bk, wv, bv, wo, bo
// Launch order puts attn_mma16 at index 5 so ncu (-s 5 -c 1) profiles it.
// ---------------------------------------------------------------------------
extern "C" void kernel_launch(void* const* d_in, const int* in_sizes, int n_in,
                              void* d_out, int out_size) {
    const float* x = (const float*)d_in[0];
    const float* y = (const float*)d_in[1];
    const unsigned char* mask = (const unsigned char*)d_in[2];
    const float* wq = (const float*)d_in[3];
    const float* bq = (const float*)d_in[4];
    const float* wk = (const float*)d_in[5];
    const float* bk = (const float*)d_in[6];
    const float* wv = (const float*)d_in[7];
    const float* bv = (const float*)d_in[8];
    const float* wo = (const float*)d_in[9];
    const float* bo = (const float*)d_in[10];
    float* out = (float*)d_out;

    // 0, 1: mask
    detect_mask_kernel<<<1, 256>>>(mask);
    convert_mask_kernel<<<(Bb * Tt + 255) / 256, 256>>>(mask);

    // 2: activation splits (x, y)
    {
        dim3 ga((NACT / 4) / 256, 1, 2);
        splitact_kernel<<<ga, 256>>>((const float4*)x, (const float4*)y);
    }
    // 3: weight splits (wq, wk, wv, wo)
    {
        dim3 gw((NWGT / 4) / 256, 1, 4);
        splitw_kernel<<<gw, 256>>>((const float4*)wq, (const float4*)wk,
                                   (const float4*)wv, (const float4*)wo);
    }

    cudaFuncSetAttribute(gemm_qkv, cudaFuncAttributeMaxDynamicSharedMemorySize, GF_SMEM);
    cudaFuncSetAttribute(gemm_out, cudaFuncAttributeMaxDynamicSharedMemorySize, GF_SMEM);

    // 4: QKV projections (fused, fp16 out)
    {
        dim3 gP(Aa / 128, (Bb * Ss) / 128, 3);
        gemm_qkv<<<gP, 256, GF_SMEM>>>(bq, bk, bv);
    }

    // 5: attention (profiled by ncu -s 5 -c 1)
    cudaFuncSetAttribute(attn_mma16, cudaFuncAttributeMaxDynamicSharedMemorySize,
                         ATT_SMEM_BYTES);
    attn_mma16<<<dim3(Ss / 128, NHEAD, Bb), 256, ATT_SMEM_BYTES>>>();

    // 6: output projection (fp32 out)
    {
        dim3 gO(Hh / 128, (Bb * Ss) / 128);
        gemm_out<<<gO, 256, GF_SMEM>>>(bo, out);
    }
}

// round 16
// speedup vs baseline: 7.8876x; 1.6196x over previous
#include <cuda_runtime.h>
#include <cuda_bf16.h>
#include <cuda_fp16.h>
#include <math.h>
#include <stdint.h>

// Problem constants
#define Bb 4
#define Ss 2048
#define Tt 2048
#define Hh 1024
#define Aa 1024
#define NHEAD 16
#define HDIM 64

// ---------------------------------------------------------------------------
// Scratch (device globals). Everything fp16 now.
// ---------------------------------------------------------------------------
#define NACT (8192 * 1024)
#define NWGT (1024 * 1024)
__device__ __half g_x16[NACT];
__device__ __half g_y16[NACT];
__device__ __half g_wq16[NWGT];
__device__ __half g_wk16[NWGT];
__device__ __half g_wv16[NWGT];
__device__ __half g_wo16[NWGT];
__device__ __half g_q16[NACT];
__device__ __half g_k16[NACT];
__device__ __half g_v16[NACT];
__device__ __half g_o16[NACT];
__device__ float d_maskf[Bb * Tt];
__device__ int d_maskmode;

// ---------------------------------------------------------------------------
// PTX helpers
// ---------------------------------------------------------------------------
__device__ __forceinline__ unsigned pack2h(float lo, float hi) {
    unsigned r;
    asm("cvt.rn.f16x2.f32 %0, %1, %2;" : "=r"(r) : "f"(hi), "f"(lo));
    return r;
}
__device__ __forceinline__ void mma16816h(float* c, const unsigned* a, const unsigned* b) {
    asm volatile(
        "mma.sync.aligned.m16n8k16.row.col.f32.f16.f16.f32 "
        "{%0,%1,%2,%3}, {%4,%5,%6,%7}, {%8,%9}, {%0,%1,%2,%3};\n"
        : "+f"(c[0]), "+f"(c[1]), "+f"(c[2]), "+f"(c[3])
        : "r"(a[0]), "r"(a[1]), "r"(a[2]), "r"(a[3]), "r"(b[0]), "r"(b[1]));
}
__device__ __forceinline__ unsigned s2u(const void* p) {
    return (unsigned)__cvta_generic_to_shared(p);
}
__device__ __forceinline__ void ldsm4(unsigned* r, unsigned addr) {
    asm volatile("ldmatrix.sync.aligned.m8n8.x4.shared.b16 {%0,%1,%2,%3}, [%4];\n"
                 : "=r"(r[0]), "=r"(r[1]), "=r"(r[2]), "=r"(r[3]) : "r"(addr));
}
__device__ __forceinline__ void ldsm4t(unsigned* r, unsigned addr) {
    asm volatile("ldmatrix.sync.aligned.m8n8.x4.trans.shared.b16 {%0,%1,%2,%3}, [%4];\n"
                 : "=r"(r[0]), "=r"(r[1]), "=r"(r[2]), "=r"(r[3]) : "r"(addr));
}
__device__ __forceinline__ void cpasync16(unsigned sdst, const void* gsrc) {
    asm volatile("cp.async.cg.shared.global [%0], [%1], 16;\n" :: "r"(sdst), "l"(gsrc));
}
#define CP_COMMIT asm volatile("cp.async.commit_group;\n")
#define CP_WAIT0 asm volatile("cp.async.wait_group 0;\n")
#define CP_WAIT1 asm volatile("cp.async.wait_group 1;\n")

// ---------------------------------------------------------------------------
// Mask dtype detection (bool8 / int32 / float32) + conversion
// ---------------------------------------------------------------------------
__global__ void detect_mask_kernel(const unsigned char* __restrict__ m) {
    const unsigned int* w = (const unsigned int*)m;
    int okf = 1, oki = 1, anyf = 0;
    for (int i = threadIdx.x; i < 2048; i += blockDim.x) {
        unsigned int v = w[i];
        if (v != 0u && v != 0x3F800000u) okf = 0;
        if (v == 0x3F800000u) anyf = 1;
        if (v > 1u) oki = 0;
    }
    okf = __syncthreads_and(okf);
    anyf = __syncthreads_or(anyf);
    oki = __syncthreads_and(oki);
    if (threadIdx.x == 0) d_maskmode = (okf && anyf) ? 0 : (oki ? 1 : 2);
}

__global__ void convert_mask_kernel(const unsigned char* __restrict__ m) {
    int i = blockIdx.x * blockDim.x + threadIdx.x;
    if (i >= Bb * Tt) return;
    int mode = d_maskmode;
    float v;
    if (mode == 0)      v = ((const float*)m)[i];
    else if (mode == 1) v = (float)((const int*)m)[i];
    else                v = (float)m[i];
    d_maskf[i] = (v != 0.0f) ? 1.0f : 0.0f;
}

// ---------------------------------------------------------------------------
// fp32 -> fp16 conversion. Fused over tensors via blockIdx.z.
// ---------------------------------------------------------------------------
__device__ __forceinline__ void cvt_body(const float4* src, uint2* dst, int i) {
    float4 v = src[i];
    dst[i] = make_uint2(pack2h(v.x, v.y), pack2h(v.z, v.w));
}

__global__ void cvtact_kernel(const float4* __restrict__ x, const float4* __restrict__ y) {
    int i = blockIdx.x * blockDim.x + threadIdx.x;
    if (blockIdx.z == 0) cvt_body(x, (uint2*)g_x16, i);
    else                 cvt_body(y, (uint2*)g_y16, i);
}

__global__ void cvtw_kernel(const float4* __restrict__ wq, const float4* __restrict__ wk,
                            const float4* __restrict__ wv, const float4* __restrict__ wo) {
    int i = blockIdx.x * blockDim.x + threadIdx.x;
    switch (blockIdx.z) {
        case 0: cvt_body(wq, (uint2*)g_wq16, i); break;
        case 1: cvt_body(wk, (uint2*)g_wk16, i); break;
        case 2: cvt_body(wv, (uint2*)g_wv16, i); break;
        default: cvt_body(wo, (uint2*)g_wo16, i); break;
    }
}

// ---------------------------------------------------------------------------
// fp16 tensor-core GEMM: C = A @ W + bias (fp32 accum).
// Block 128x128, BK=32, 8 warps (2x4), warp tile 64x32, mma m16n8k16.
// Output: fp16 (C16) if non-null, else fp32 (Cf).
// ---------------------------------------------------------------------------
#define H_GA (128 * 40)
#define H_GW (32 * 136)
#define H_STAGE (H_GA + H_GW)
#define H_SMEM (2 * H_STAGE * (int)sizeof(__half))

__device__ __forceinline__ void gemm_core16(
        const __half* __restrict__ A, const __half* __restrict__ W,
        const float* __restrict__ bias, __half* __restrict__ C16,
        float* __restrict__ Cf, int M, int N, int K, __half* gsm) {
    const int tid = threadIdx.x;
    const int wid = tid >> 5, lane = tid & 31;
    const int wm = wid >> 2, wn = wid & 3;
    const int g = lane >> 2, tig = lane & 3;
    const int row0 = blockIdx.y * 128, col0 = blockIdx.x * 128;

    float acc[4][4][4];
#pragma unroll
    for (int i = 0; i < 4; i++)
#pragma unroll
        for (int j = 0; j < 4; j++)
#pragma unroll
            for (int k = 0; k < 4; k++) acc[i][j][k] = 0.f;

    auto load_stage = [&](int st, int k0) {
        __half* AS = gsm + st * H_STAGE;
        __half* WS = AS + H_GA;
#pragma unroll
        for (int l = 0; l < 2; l++) {
            int c = tid + l * 256;
            int ar = c >> 2, ac = (c & 3) * 8;
            cpasync16(s2u(&AS[ar * 40 + ac]), A + (size_t)(row0 + ar) * K + k0 + ac);
            int wr = c >> 4, wc = (c & 15) * 8;
            cpasync16(s2u(&WS[wr * 136 + wc]), W + (size_t)(k0 + wr) * N + col0 + wc);
        }
    };

    load_stage(0, 0);
    CP_COMMIT;

    int stage = 0;
    for (int k0 = 0; k0 < K; k0 += 32) {
        if (k0 + 32 < K) {
            load_stage(stage ^ 1, k0 + 32);
            CP_COMMIT;
            CP_WAIT1;
        } else {
            CP_WAIT0;
        }
        __syncthreads();

        const __half* AS = gsm + stage * H_STAGE;
        const __half* WS = AS + H_GA;

#pragma unroll
        for (int kk = 0; kk < 32; kk += 16) {
            const int arow = wm * 64 + (lane & 15);
            const int aoff = kk + 8 * (lane >> 4);
            const int wrow = kk + (lane & 15);
            const int woff = wn * 32 + 8 * (lane >> 4);

            unsigned wf[2][4];
#pragma unroll
            for (int n2 = 0; n2 < 2; n2++)
                ldsm4t(wf[n2], s2u(&WS[wrow * 136 + woff + n2 * 16]));
#pragma unroll
            for (int mf = 0; mf < 4; mf++) {
                unsigned af[4];
                ldsm4(af, s2u(&AS[(arow + mf * 16) * 40 + aoff]));
#pragma unroll
                for (int nf = 0; nf < 4; nf++)
                    mma16816h(acc[mf][nf], af, &wf[nf >> 1][(nf & 1) * 2]);
            }
        }
        __syncthreads();
        stage ^= 1;
    }

#pragma unroll
    for (int mf = 0; mf < 4; mf++) {
        size_t r1 = (size_t)(row0 + wm * 64 + mf * 16 + g);
#pragma unroll
        for (int nf = 0; nf < 4; nf++) {
            int c = col0 + wn * 32 + nf * 8 + tig * 2;
            float2 b2 = *(const float2*)&bias[c];
            float v00 = acc[mf][nf][0] + b2.x, v01 = acc[mf][nf][1] + b2.y;
            float v10 = acc[mf][nf][2] + b2.x, v11 = acc[mf][nf][3] + b2.y;
            if (C16) {
                *(unsigned*)(C16 + r1 * N + c) = pack2h(v00, v01);
                *(unsigned*)(C16 + (r1 + 8) * N + c) = pack2h(v10, v11);
            } else {
                *(float2*)&Cf[r1 * N + c] = make_float2(v00, v01);
                *(float2*)&Cf[(r1 + 8) * N + c] = make_float2(v10, v11);
            }
        }
    }
}

// QKV fused: blockIdx.z selects projection.
__global__ __launch_bounds__(256, 2)
void gemm_qkv(const float* __restrict__ bq, const float* __restrict__ bk,
              const float* __restrict__ bv) {
    extern __shared__ __half gsm[];
    const __half *A, *W;
    const float* bias;
    __half* C16;
    if (blockIdx.z == 0) { A = g_x16; W = g_wq16; bias = bq; C16 = g_q16; }
    else if (blockIdx.z == 1) { A = g_y16; W = g_wk16; bias = bk; C16 = g_k16; }
    else { A = g_y16; W = g_wv16; bias = bv; C16 = g_v16; }
    gemm_core16(A, W, bias, C16, nullptr, Bb * Ss, Aa, Hh, gsm);
}

__global__ __launch_bounds__(256, 2)
void gemm_out(const float* __restrict__ bo, float* __restrict__ out) {
    extern __shared__ __half gsm[];
    gemm_core16(g_o16, g_wo16, bo, nullptr, out, Bb * Ss, Hh, Aa, gsm);
}

// ---------------------------------------------------------------------------
// Flash attention, pure fp16 operands (fp32 accum + fp32 softmax).
// Block: 128 q-rows, 8 warps (16 rows each, full t=64 -> warp-local softmax).
// Double-buffered cp.async K/V fp16 tiles. (Identical mainloop to R15.)
// ---------------------------------------------------------------------------
#define AT_PAD 72
#define AT_TILE (64 * AT_PAD)
#define AT_BUF (2 * AT_TILE)
#define ATT_SMEM_BYTES (2 * AT_BUF * 2)

__global__ __launch_bounds__(256)
void attn_mma16() {
    extern __shared__ __half smh[];
    const int sq = blockIdx.x, h = blockIdx.y, b = blockIdx.z;
    const int tid = threadIdx.x, wid = tid >> 5, lane = tid & 31;
    const int g = lane >> 2, tig = lane & 3;

    unsigned qf[4][4];
    {
        size_t rbase = ((size_t)b * Ss + sq * 128 + wid * 16) * Aa + h * HDIM;
        size_t o00 = rbase + (size_t)g * Aa + tig * 2;
#pragma unroll
        for (int dc = 0; dc < 4; dc++) {
            size_t o = o00 + dc * 16;
            qf[dc][0] = *(const unsigned*)(g_q16 + o);
            qf[dc][1] = *(const unsigned*)(g_q16 + o + (size_t)8 * Aa);
            qf[dc][2] = *(const unsigned*)(g_q16 + o + 8);
            qf[dc][3] = *(const unsigned*)(g_q16 + o + (size_t)8 * Aa + 8);
        }
    }

    float oacc[8][4];
#pragma unroll
    for (int i = 0; i < 8; i++)
#pragma unroll
        for (int j = 0; j < 4; j++) oacc[i][j] = 0.f;
    float mo0 = -INFINITY, mo1 = -INFINITY, l0 = 0.f, l1 = 0.f;

    auto load_tiles = [&](int it, int bb) {
        const size_t base = ((size_t)b * Tt + it * 64) * Aa + h * HDIM;
#pragma unroll
        for (int l = 0; l < 4; l++) {
            int c = tid + l * 256;
            int mat = c >> 9, r = (c >> 3) & 63, ch = c & 7;
            const __half* src = (mat == 0 ? g_k16 : g_v16) + base + (size_t)r * Aa + ch * 8;
            cpasync16(s2u(smh + bb * AT_BUF + mat * AT_TILE + r * AT_PAD + ch * 8), src);
        }
    };

    load_tiles(0, 0);
    CP_COMMIT;
    const int NIT = Tt / 64;

#pragma unroll 1
    for (int it = 0; it < NIT; it++) {
        int bb = it & 1;
        if (it + 1 < NIT) { load_tiles(it + 1, bb ^ 1); CP_COMMIT; CP_WAIT1; }
        else               { CP_WAIT0; }
        __syncthreads();

        const __half* KS = smh + bb * AT_BUF;
        const __half* VS = KS + AT_TILE;

        float s[8][4];
#pragma unroll
        for (int i = 0; i < 8; i++)
#pragma unroll
            for (int j = 0; j < 4; j++) s[i][j] = 0.f;

        const int ktrow = ((lane >> 4) & 1) * 8 + (lane & 7);
        const int kdoff = ((lane >> 3) & 1) * 8;
#pragma unroll
        for (int dc = 0; dc < 4; dc++) {
#pragma unroll
            for (int j = 0; j < 4; j++) {
                unsigned kf[4];
                ldsm4(kf, s2u(KS + (j * 16 + ktrow) * AT_PAD + dc * 16 + kdoff));
                mma16816h(s[2 * j], qf[dc], kf);
                mma16816h(s[2 * j + 1], qf[dc], kf + 2);
            }
        }

        const float* mrow = d_maskf + b * Tt + it * 64;
        float mt0 = -INFINITY, mt1 = -INFINITY;
#pragma unroll
        for (int n = 0; n < 8; n++) {
            float2 m2 = *(const float2*)&mrow[n * 8 + tig * 2];
            s[n][0] = (m2.x != 0.f) ? s[n][0] * 0.125f : -100000.0f;
            s[n][1] = (m2.y != 0.f) ? s[n][1] * 0.125f : -100000.0f;
            s[n][2] = (m2.x != 0.f) ? s[n][2] * 0.125f : -100000.0f;
            s[n][3] = (m2.y != 0.f) ? s[n][3] * 0.125f : -100000.0f;
            mt0 = fmaxf(mt0, fmaxf(s[n][0], s[n][1]));
            mt1 = fmaxf(mt1, fmaxf(s[n][2], s[n][3]));
        }
        mt0 = fmaxf(mt0, __shfl_xor_sync(0xFFFFFFFFu, mt0, 1));
        mt0 = fmaxf(mt0, __shfl_xor_sync(0xFFFFFFFFu, mt0, 2));
        mt1 = fmaxf(mt1, __shfl_xor_sync(0xFFFFFFFFu, mt1, 1));
        mt1 = fmaxf(mt1, __shfl_xor_sync(0xFFFFFFFFu, mt1, 2));
        float mn0 = fmaxf(mo0, mt0), mn1 = fmaxf(mo1, mt1);
        float a0 = __expf(mo0 - mn0), a1 = __expf(mo1 - mn1);
        float ls0 = 0.f, ls1 = 0.f;
#pragma unroll
        for (int n = 0; n < 8; n++) {
            s[n][0] = __expf(s[n][0] - mn0);
            s[n][1] = __expf(s[n][1] - mn0);
            s[n][2] = __expf(s[n][2] - mn1);
            s[n][3] = __expf(s[n][3] - mn1);
            ls0 += s[n][0] + s[n][1];
            ls1 += s[n][2] + s[n][3];
        }
        ls0 += __shfl_xor_sync(0xFFFFFFFFu, ls0, 1);
        ls0 += __shfl_xor_sync(0xFFFFFFFFu, ls0, 2);
        ls1 += __shfl_xor_sync(0xFFFFFFFFu, ls1, 1);
        ls1 += __shfl_xor_sync(0xFFFFFFFFu, ls1, 2);
        l0 = l0 * a0 + ls0;
        l1 = l1 * a1 + ls1;
#pragma unroll
        for (int nd = 0; nd < 8; nd++) {
            oacc[nd][0] *= a0; oacc[nd][1] *= a0;
            oacc[nd][2] *= a1; oacc[nd][3] *= a1;
        }
        mo0 = mn0; mo1 = mn1;

        const int vtrow = lane & 15;
        const int vdoff = (lane >> 4) * 8;
#pragma unroll
        for (int tc = 0; tc < 4; tc++) {
            unsigned pf[4];
            pf[0] = pack2h(s[2 * tc][0], s[2 * tc][1]);
            pf[1] = pack2h(s[2 * tc][2], s[2 * tc][3]);
            pf[2] = pack2h(s[2 * tc + 1][0], s[2 * tc + 1][1]);
            pf[3] = pack2h(s[2 * tc + 1][2], s[2 * tc + 1][3]);
#pragma unroll
            for (int dj = 0; dj < 4; dj++) {
                unsigned vf[4];
                ldsm4t(vf, s2u(VS + (tc * 16 + vtrow) * AT_PAD + dj * 16 + vdoff));
                mma16816h(oacc[2 * dj], pf, vf);
                mma16816h(oacc[2 * dj + 1], pf, vf + 2);
            }
        }
        __syncthreads();
    }

    // epilogue: O/l -> fp16 for the output GEMM
    float i0 = 1.0f / l0, i1 = 1.0f / l1;
    size_t r0o = ((size_t)b * Ss + sq * 128 + wid * 16 + g) * Aa + h * HDIM;
#pragma unroll
    for (int nd = 0; nd < 8; nd++) {
        int c = nd * 8 + tig * 2;
        *(unsigned*)(g_o16 + r0o + c) = pack2h(oacc[nd][0] * i0, oacc[nd][1] * i0);
        *(unsigned*)(g_o16 + r0o + (size_t)8 * Aa + c) =
            pack2h(oacc[nd][2] * i1, oacc[nd][3] * i1);
    }
}

// ---------------------------------------------------------------------------
// Launch. Inputs: x, y, mask, wq, bq, wk, bk, wv, bv, wo, bo
// attn_mma16 stays at launch index 5 for ncu (-s 5 -c 1).
// ---------------------------------------------------------------------------
extern "C" void kernel_launch(void* const* d_in, const int* in_sizes, int n_in,
                              void* d_out, int out_size) {
    const float* x = (const float*)d_in[0];
    const float* y = (const float*)d_in[1];
    const unsigned char* mask = (const unsigned char*)d_in[2];
    const float* wq = (const float*)d_in[3];
    const float* bq = (const float*)d_in[4];
    const float* wk = (const float*)d_in[5];
    const float* bk = (const float*)d_in[6];
    const float* wv = (const float*)d_in[7];
    const float* bv = (const float*)d_in[8];
    const float* wo = (const float*)d_in[9];
    const float* bo = (const float*)d_in[10];
    float* out = (float*)d_out;

    // 0, 1: mask
    detect_mask_kernel<<<1, 256>>>(mask);
    convert_mask_kernel<<<(Bb * Tt + 255) / 256, 256>>>(mask);

    // 2: activation conversion (x, y)
    {
        dim3 ga((NACT / 4) / 256, 1, 2);
        cvtact_kernel<<<ga, 256>>>((const float4*)x, (const float4*)y);
    }
    // 3: weight conversion (wq, wk, wv, wo)
    {
        dim3 gw((NWGT / 4) / 256, 1, 4);
        cvtw_kernel<<<gw, 256>>>((const float4*)wq, (const float4*)wk,
                                 (const float4*)wv, (const float4*)wo);
    }

    cudaFuncSetAttribute(gemm_qkv, cudaFuncAttributeMaxDynamicSharedMemorySize, H_SMEM);
    cudaFuncSetAttribute(gemm_out, cudaFuncAttributeMaxDynamicSharedMemorySize, H_SMEM);

    // 4: QKV projections (fused)
    {
        dim3 gP(Aa / 128, (Bb * Ss) / 128, 3);
        gemm_qkv<<<gP, 256, H_SMEM>>>(bq, bk, bv);
    }

    // 5: attention (profiled by ncu -s 5 -c 1)
    cudaFuncSetAttribute(attn_mma16, cudaFuncAttributeMaxDynamicSharedMemorySize,
                         ATT_SMEM_BYTES);
    attn_mma16<<<dim3(Ss / 128, NHEAD, Bb), 256, ATT_SMEM_BYTES>>>();

    // 6: output projection (fp32 out)
    {
        dim3 gO(Hh / 128, (Bb * Ss) / 128);
        gemm_out<<<gO, 256, H_SMEM>>>(bo, out);
    }
}

// round 17
// speedup vs baseline: 8.2712x; 1.0486x over previous
#include <cuda_runtime.h>
#include <cuda_bf16.h>
#include <cuda_fp16.h>
#include <math.h>
#include <stdint.h>

// Problem constants
#define Bb 4
#define Ss 2048
#define Tt 2048
#define Hh 1024
#define Aa 1024
#define NHEAD 16
#define HDIM 64

// 0.125 * log2(e): folded into wq/bq so QK^T lands in exp2 domain, pre-scaled.
#define QSCALE 0.18033688011112042f
// -100000 * log2(e): mask value in exp2 domain.
#define MASKVAL -144269.5f

// ---------------------------------------------------------------------------
// Scratch (device globals). Everything fp16.
// ---------------------------------------------------------------------------
#define NACT (8192 * 1024)
#define NWGT (1024 * 1024)
__device__ __half g_x16[NACT];
__device__ __half g_y16[NACT];
__device__ __half g_wq16[NWGT];
__device__ __half g_wk16[NWGT];
__device__ __half g_wv16[NWGT];
__device__ __half g_wo16[NWGT];
__device__ __half g_q16[NACT];
__device__ __half g_k16[NACT];
__device__ __half g_v16[NACT];
__device__ __half g_o16[NACT];
__device__ float d_maskf[Bb * Tt];
__device__ int d_maskmode;

// ---------------------------------------------------------------------------
// PTX helpers
// ---------------------------------------------------------------------------
__device__ __forceinline__ unsigned pack2h(float lo, float hi) {
    unsigned r;
    asm("cvt.rn.f16x2.f32 %0, %1, %2;" : "=r"(r) : "f"(hi), "f"(lo));
    return r;
}
__device__ __forceinline__ float ex2f(float x) {
    float r;
    asm("ex2.approx.f32 %0, %1;" : "=f"(r) : "f"(x));
    return r;
}
__device__ __forceinline__ void mma16816h(float* c, const unsigned* a, const unsigned* b) {
    asm volatile(
        "mma.sync.aligned.m16n8k16.row.col.f32.f16.f16.f32 "
        "{%0,%1,%2,%3}, {%4,%5,%6,%7}, {%8,%9}, {%0,%1,%2,%3};\n"
        : "+f"(c[0]), "+f"(c[1]), "+f"(c[2]), "+f"(c[3])
        : "r"(a[0]), "r"(a[1]), "r"(a[2]), "r"(a[3]), "r"(b[0]), "r"(b[1]));
}
__device__ __forceinline__ unsigned s2u(const void* p) {
    return (unsigned)__cvta_generic_to_shared(p);
}
__device__ __forceinline__ void ldsm4(unsigned* r, unsigned addr) {
    asm volatile("ldmatrix.sync.aligned.m8n8.x4.shared.b16 {%0,%1,%2,%3}, [%4];\n"
                 : "=r"(r[0]), "=r"(r[1]), "=r"(r[2]), "=r"(r[3]) : "r"(addr));
}
__device__ __forceinline__ void ldsm4t(unsigned* r, unsigned addr) {
    asm volatile("ldmatrix.sync.aligned.m8n8.x4.trans.shared.b16 {%0,%1,%2,%3}, [%4];\n"
                 : "=r"(r[0]), "=r"(r[1]), "=r"(r[2]), "=r"(r[3]) : "r"(addr));
}
__device__ __forceinline__ void cpasync16(unsigned sdst, const void* gsrc) {
    asm volatile("cp.async.cg.shared.global [%0], [%1], 16;\n" :: "r"(sdst), "l"(gsrc));
}
#define CP_COMMIT asm volatile("cp.async.commit_group;\n")
#define CP_WAIT0 asm volatile("cp.async.wait_group 0;\n")
#define CP_WAIT1 asm volatile("cp.async.wait_group 1;\n")

// ---------------------------------------------------------------------------
// Mask dtype detection (bool8 / int32 / float32) + conversion
// ---------------------------------------------------------------------------
__global__ void detect_mask_kernel(const unsigned char* __restrict__ m) {
    const unsigned int* w = (const unsigned int*)m;
    int okf = 1, oki = 1, anyf = 0;
    for (int i = threadIdx.x; i < 2048; i += blockDim.x) {
        unsigned int v = w[i];
        if (v != 0u && v != 0x3F800000u) okf = 0;
        if (v == 0x3F800000u) anyf = 1;
        if (v > 1u) oki = 0;
    }
    okf = __syncthreads_and(okf);
    anyf = __syncthreads_or(anyf);
    oki = __syncthreads_and(oki);
    if (threadIdx.x == 0) d_maskmode = (okf && anyf) ? 0 : (oki ? 1 : 2);
}

__global__ void convert_mask_kernel(const unsigned char* __restrict__ m) {
    int i = blockIdx.x * blockDim.x + threadIdx.x;
    if (i >= Bb * Tt) return;
    int mode = d_maskmode;
    float v;
    if (mode == 0)      v = ((const float*)m)[i];
    else if (mode == 1) v = (float)((const int*)m)[i];
    else                v = (float)m[i];
    d_maskf[i] = (v != 0.0f) ? 1.0f : 0.0f;
}

// ---------------------------------------------------------------------------
// fp32 -> fp16 conversion (optional scale). Fused over tensors via blockIdx.z.
// ---------------------------------------------------------------------------
__device__ __forceinline__ void cvt_body(const float4* src, uint2* dst, int i, float sc) {
    float4 v = src[i];
    dst[i] = make_uint2(pack2h(v.x * sc, v.y * sc), pack2h(v.z * sc, v.w * sc));
}

__global__ void cvtact_kernel(const float4* __restrict__ x, const float4* __restrict__ y) {
    int i = blockIdx.x * blockDim.x + threadIdx.x;
    if (blockIdx.z == 0) cvt_body(x, (uint2*)g_x16, i, 1.0f);
    else                 cvt_body(y, (uint2*)g_y16, i, 1.0f);
}

__global__ void cvtw_kernel(const float4* __restrict__ wq, const float4* __restrict__ wk,
                            const float4* __restrict__ wv, const float4* __restrict__ wo) {
    int i = blockIdx.x * blockDim.x + threadIdx.x;
    switch (blockIdx.z) {
        case 0: cvt_body(wq, (uint2*)g_wq16, i, QSCALE); break;  // fold QK scale
        case 1: cvt_body(wk, (uint2*)g_wk16, i, 1.0f); break;
        case 2: cvt_body(wv, (uint2*)g_wv16, i, 1.0f); break;
        default: cvt_body(wo, (uint2*)g_wo16, i, 1.0f); break;
    }
}

// ---------------------------------------------------------------------------
// fp16 tensor-core GEMM: C = A @ W + bias*bscale (fp32 accum).
// Block 128x128, BK=32, 8 warps, warp tile 64x32, mma m16n8k16.
// 3-stage cp.async pipeline, ONE __syncthreads per K-iter.
// ---------------------------------------------------------------------------
#define H_GA (128 * 40)
#define H_GW (32 * 136)
#define H_STAGE (H_GA + H_GW)
#define H_SMEM (3 * H_STAGE * (int)sizeof(__half))

__device__ __forceinline__ void gemm_core16(
        const __half* __restrict__ A, const __half* __restrict__ W,
        const float* __restrict__ bias, float bscale, __half* __restrict__ C16,
        float* __restrict__ Cf, int M, int N, int K, __half* gsm) {
    const int tid = threadIdx.x;
    const int wid = tid >> 5, lane = tid & 31;
    const int wm = wid >> 2, wn = wid & 3;
    const int g = lane >> 2, tig = lane & 3;
    const int row0 = blockIdx.y * 128, col0 = blockIdx.x * 128;

    float acc[4][4][4];
#pragma unroll
    for (int i = 0; i < 4; i++)
#pragma unroll
        for (int j = 0; j < 4; j++)
#pragma unroll
            for (int k = 0; k < 4; k++) acc[i][j][k] = 0.f;

    auto load_stage = [&](int st, int k0) {
        __half* AS = gsm + st * H_STAGE;
        __half* WS = AS + H_GA;
#pragma unroll
        for (int l = 0; l < 2; l++) {
            int c = tid + l * 256;
            int ar = c >> 2, ac = (c & 3) * 8;
            cpasync16(s2u(&AS[ar * 40 + ac]), A + (size_t)(row0 + ar) * K + k0 + ac);
            int wr = c >> 4, wc = (c & 15) * 8;
            cpasync16(s2u(&WS[wr * 136 + wc]), W + (size_t)(k0 + wr) * N + col0 + wc);
        }
    };

    const int NIT = K / 32;
    load_stage(0, 0);
    CP_COMMIT;
    load_stage(1, 32);
    CP_COMMIT;

    const int arow = wm * 64 + (lane & 15);
    const int aoff0 = 8 * (lane >> 4);
    const int wrow0 = (lane & 15);
    const int woff = wn * 32 + 8 * (lane >> 4);

#pragma unroll 1
    for (int it = 0; it < NIT; it++) {
        const int st = it % 3;
        if (it < NIT - 1) { CP_WAIT1; } else { CP_WAIT0; }
        __syncthreads();
        if (it + 2 < NIT) {
            load_stage((st + 2) % 3, (it + 2) * 32);
            CP_COMMIT;
        }

        const __half* AS = gsm + st * H_STAGE;
        const __half* WS = AS + H_GA;

#pragma unroll
        for (int kk = 0; kk < 32; kk += 16) {
            unsigned wf[2][4];
#pragma unroll
            for (int n2 = 0; n2 < 2; n2++)
                ldsm4t(wf[n2], s2u(&WS[(kk + wrow0) * 136 + woff + n2 * 16]));
#pragma unroll
            for (int mf = 0; mf < 4; mf++) {
                unsigned af[4];
                ldsm4(af, s2u(&AS[(arow + mf * 16) * 40 + kk + aoff0]));
#pragma unroll
                for (int nf = 0; nf < 4; nf++)
                    mma16816h(acc[mf][nf], af, &wf[nf >> 1][(nf & 1) * 2]);
            }
        }
    }

#pragma unroll
    for (int mf = 0; mf < 4; mf++) {
        size_t r1 = (size_t)(row0 + wm * 64 + mf * 16 + g);
#pragma unroll
        for (int nf = 0; nf < 4; nf++) {
            int c = col0 + wn * 32 + nf * 8 + tig * 2;
            float2 b2 = *(const float2*)&bias[c];
            b2.x *= bscale; b2.y *= bscale;
            float v00 = acc[mf][nf][0] + b2.x, v01 = acc[mf][nf][1] + b2.y;
            float v10 = acc[mf][nf][2] + b2.x, v11 = acc[mf][nf][3] + b2.y;
            if (C16) {
                *(unsigned*)(C16 + r1 * N + c) = pack2h(v00, v01);
                *(unsigned*)(C16 + (r1 + 8) * N + c) = pack2h(v10, v11);
            } else {
                *(float2*)&Cf[r1 * N + c] = make_float2(v00, v01);
                *(float2*)&Cf[(r1 + 8) * N + c] = make_float2(v10, v11);
            }
        }
    }
}

// QKV fused: blockIdx.z selects projection. Q path carries QSCALE on bias.
__global__ __launch_bounds__(256, 2)
void gemm_qkv(const float* __restrict__ bq, const float* __restrict__ bk,
              const float* __restrict__ bv) {
    extern __shared__ __half gsm[];
    const __half *A, *W;
    const float* bias;
    __half* C16;
    float bsc = 1.0f;
    if (blockIdx.z == 0) { A = g_x16; W = g_wq16; bias = bq; C16 = g_q16; bsc = QSCALE; }
    else if (blockIdx.z == 1) { A = g_y16; W = g_wk16; bias = bk; C16 = g_k16; }
    else { A = g_y16; W = g_wv16; bias = bv; C16 = g_v16; }
    gemm_core16(A, W, bias, bsc, C16, nullptr, Bb * Ss, Aa, Hh, gsm);
}

__global__ __launch_bounds__(256, 2)
void gemm_out(const float* __restrict__ bo, float* __restrict__ out) {
    extern __shared__ __half gsm[];
    gemm_core16(g_o16, g_wo16, bo, 1.0f, nullptr, out, Bb * Ss, Hh, Aa, gsm);
}

// ---------------------------------------------------------------------------
// Flash attention, fp16 operands, softmax in exp2 domain (Q pre-scaled by
// 0.125*log2e). 3-stage cp.async pipeline, ONE __syncthreads per iter.
// ---------------------------------------------------------------------------
#define AT_PAD 72
#define AT_TILE (64 * AT_PAD)
#define AT_BUF (2 * AT_TILE)            // K, V halves per stage
#define ATT_SMEM_BYTES (3 * AT_BUF * 2) // 55296 B

__global__ __launch_bounds__(256)
void attn_mma16() {
    extern __shared__ __half smh[];
    const int sq = blockIdx.x, h = blockIdx.y, b = blockIdx.z;
    const int tid = threadIdx.x, wid = tid >> 5, lane = tid & 31;
    const int g = lane >> 2, tig = lane & 3;

    unsigned qf[4][4];
    {
        size_t rbase = ((size_t)b * Ss + sq * 128 + wid * 16) * Aa + h * HDIM;
        size_t o00 = rbase + (size_t)g * Aa + tig * 2;
#pragma unroll
        for (int dc = 0; dc < 4; dc++) {
            size_t o = o00 + dc * 16;
            qf[dc][0] = *(const unsigned*)(g_q16 + o);
            qf[dc][1] = *(const unsigned*)(g_q16 + o + (size_t)8 * Aa);
            qf[dc][2] = *(const unsigned*)(g_q16 + o + 8);
            qf[dc][3] = *(const unsigned*)(g_q16 + o + (size_t)8 * Aa + 8);
        }
    }

    float oacc[8][4];
#pragma unroll
    for (int i = 0; i < 8; i++)
#pragma unroll
        for (int j = 0; j < 4; j++) oacc[i][j] = 0.f;
    float mo0 = -INFINITY, mo1 = -INFINITY, l0 = 0.f, l1 = 0.f;

    auto load_tiles = [&](int it, int st) {
        const size_t base = ((size_t)b * Tt + it * 64) * Aa + h * HDIM;
#pragma unroll
        for (int l = 0; l < 4; l++) {
            int c = tid + l * 256;
            int mat = c >> 9, r = (c >> 3) & 63, ch = c & 7;
            const __half* src = (mat == 0 ? g_k16 : g_v16) + base + (size_t)r * Aa + ch * 8;
            cpasync16(s2u(smh + st * AT_BUF + mat * AT_TILE + r * AT_PAD + ch * 8), src);
        }
    };

    const int NIT = Tt / 64;
    load_tiles(0, 0);
    CP_COMMIT;
    load_tiles(1, 1);
    CP_COMMIT;

    const float* mbase = d_maskf + b * Tt;
    const int ktrow = ((lane >> 4) & 1) * 8 + (lane & 7);
    const int kdoff = ((lane >> 3) & 1) * 8;
    const int vtrow = lane & 15;
    const int vdoff = (lane >> 4) * 8;

#pragma unroll 1
    for (int it = 0; it < NIT; it++) {
        const int st = it % 3;
        // mask (independent of smem) before the sync
        float2 mk[8];
#pragma unroll
        for (int n = 0; n < 8; n++)
            mk[n] = *(const float2*)&mbase[it * 64 + n * 8 + tig * 2];

        if (it < NIT - 1) { CP_WAIT1; } else { CP_WAIT0; }
        __syncthreads();
        if (it + 2 < NIT) {
            load_tiles(it + 2, (it + 2) % 3);
            CP_COMMIT;
        }

        const __half* KS = smh + st * AT_BUF;
        const __half* VS = KS + AT_TILE;

        // ---- S' = Q' K^T (exp2-domain logits) ----
        float s[8][4];
#pragma unroll
        for (int i = 0; i < 8; i++)
#pragma unroll
            for (int j = 0; j < 4; j++) s[i][j] = 0.f;

#pragma unroll
        for (int dc = 0; dc < 4; dc++) {
#pragma unroll
            for (int j = 0; j < 4; j++) {
                unsigned kf[4];
                ldsm4(kf, s2u(KS + (j * 16 + ktrow) * AT_PAD + dc * 16 + kdoff));
                mma16816h(s[2 * j], qf[dc], kf);
                mma16816h(s[2 * j + 1], qf[dc], kf + 2);
            }
        }

        // ---- mask + online softmax (exp2 domain) ----
        float mt0 = -INFINITY, mt1 = -INFINITY;
#pragma unroll
        for (int n = 0; n < 8; n++) {
            s[n][0] = (mk[n].x != 0.f) ? s[n][0] : MASKVAL;
            s[n][1] = (mk[n].y != 0.f) ? s[n][1] : MASKVAL;
            s[n][2] = (mk[n].x != 0.f) ? s[n][2] : MASKVAL;
            s[n][3] = (mk[n].y != 0.f) ? s[n][3] : MASKVAL;
            mt0 = fmaxf(mt0, fmaxf(s[n][0], s[n][1]));
            mt1 = fmaxf(mt1, fmaxf(s[n][2], s[n][3]));
        }
        mt0 = fmaxf(mt0, __shfl_xor_sync(0xFFFFFFFFu, mt0, 1));
        mt0 = fmaxf(mt0, __shfl_xor_sync(0xFFFFFFFFu, mt0, 2));
        mt1 = fmaxf(mt1, __shfl_xor_sync(0xFFFFFFFFu, mt1, 1));
        mt1 = fmaxf(mt1, __shfl_xor_sync(0xFFFFFFFFu, mt1, 2));
        float mn0 = fmaxf(mo0, mt0), mn1 = fmaxf(mo1, mt1);
        float a0 = ex2f(mo0 - mn0), a1 = ex2f(mo1 - mn1);
        float ls0 = 0.f, ls1 = 0.f;
#pragma unroll
        for (int n = 0; n < 8; n++) {
            s[n][0] = ex2f(s[n][0] - mn0);
            s[n][1] = ex2f(s[n][1] - mn0);
            s[n][2] = ex2f(s[n][2] - mn1);
            s[n][3] = ex2f(s[n][3] - mn1);
            ls0 += s[n][0] + s[n][1];
            ls1 += s[n][2] + s[n][3];
        }
        ls0 += __shfl_xor_sync(0xFFFFFFFFu, ls0, 1);
        ls0 += __shfl_xor_sync(0xFFFFFFFFu, ls0, 2);
        ls1 += __shfl_xor_sync(0xFFFFFFFFu, ls1, 1);
        ls1 += __shfl_xor_sync(0xFFFFFFFFu, ls1, 2);
        l0 = l0 * a0 + ls0;
        l1 = l1 * a1 + ls1;
        if (a0 != 1.0f || a1 != 1.0f) {
#pragma unroll
            for (int nd = 0; nd < 8; nd++) {
                oacc[nd][0] *= a0; oacc[nd][1] *= a0;
                oacc[nd][2] *= a1; oacc[nd][3] *= a1;
            }
        }
        mo0 = mn0; mo1 = mn1;

        // ---- O += P V ----
#pragma unroll
        for (int tc = 0; tc < 4; tc++) {
            unsigned pf[4];
            pf[0] = pack2h(s[2 * tc][0], s[2 * tc][1]);
            pf[1] = pack2h(s[2 * tc][2], s[2 * tc][3]);
            pf[2] = pack2h(s[2 * tc + 1][0], s[2 * tc + 1][1]);
            pf[3] = pack2h(s[2 * tc + 1][2], s[2 * tc + 1][3]);
#pragma unroll
            for (int dj = 0; dj < 4; dj++) {
                unsigned vf[4];
                ldsm4t(vf, s2u(VS + (tc * 16 + vtrow) * AT_PAD + dj * 16 + vdoff));
                mma16816h(oacc[2 * dj], pf, vf);
                mma16816h(oacc[2 * dj + 1], pf, vf + 2);
            }
        }
    }

    // epilogue: O/l -> fp16 for the output GEMM
    float i0 = 1.0f / l0, i1 = 1.0f / l1;
    size_t r0o = ((size_t)b * Ss + sq * 128 + wid * 16 + g) * Aa + h * HDIM;
#pragma unroll
    for (int nd = 0; nd < 8; nd++) {
        int c = nd * 8 + tig * 2;
        *(unsigned*)(g_o16 + r0o + c) = pack2h(oacc[nd][0] * i0, oacc[nd][1] * i0);
        *(unsigned*)(g_o16 + r0o + (size_t)8 * Aa + c) =
            pack2h(oacc[nd][2] * i1, oacc[nd][3] * i1);
    }
}

// ---------------------------------------------------------------------------
// Launch. Inputs: x, y, mask, wq, bq, wk, bk, wv, bv, wo, bo
// attn_mma16 stays at launch index 5 for ncu (-s 5 -c 1).
// ---------------------------------------------------------------------------
extern "C" void kernel_launch(void* const* d_in, const int* in_sizes, int n_in,
                              void* d_out, int out_size) {
    const float* x = (const float*)d_in[0];
    const float* y = (const float*)d_in[1];
    const unsigned char* mask = (const unsigned char*)d_in[2];
    const float* wq = (const float*)d_in[3];
    const float* bq = (const float*)d_in[4];
    const float* wk = (const float*)d_in[5];
    const float* bk = (const float*)d_in[6];
    const float* wv = (const float*)d_in[7];
    const float* bv = (const float*)d_in[8];
    const float* wo = (const float*)d_in[9];
    const float* bo = (const float*)d_in[10];
    float* out = (float*)d_out;

    // 0, 1: mask
    detect_mask_kernel<<<1, 256>>>(mask);
    convert_mask_kernel<<<(Bb * Tt + 255) / 256, 256>>>(mask);

    // 2: activation conversion (x, y)
    {
        dim3 ga((NACT / 4) / 256, 1, 2);
        cvtact_kernel<<<ga, 256>>>((const float4*)x, (const float4*)y);
    }
    // 3: weight conversion (wq scaled, wk, wv, wo)
    {
        dim3 gw((NWGT / 4) / 256, 1, 4);
        cvtw_kernel<<<gw, 256>>>((const float4*)wq, (const float4*)wk,
                                 (const float4*)wv, (const float4*)wo);
    }

    cudaFuncSetAttribute(gemm_qkv, cudaFuncAttributeMaxDynamicSharedMemorySize, H_SMEM);
    cudaFuncSetAttribute(gemm_out, cudaFuncAttributeMaxDynamicSharedMemorySize, H_SMEM);

    // 4: QKV projections (fused)
    {
        dim3 gP(Aa / 128, (Bb * Ss) / 128, 3);
        gemm_qkv<<<gP, 256, H_SMEM>>>(bq, bk, bv);
    }

    // 5: attention (profiled by ncu -s 5 -c 1)
    cudaFuncSetAttribute(attn_mma16, cudaFuncAttributeMaxDynamicSharedMemorySize,
                         ATT_SMEM_BYTES);
    attn_mma16<<<dim3(Ss / 128, NHEAD, Bb), 256, ATT_SMEM_BYTES>>>();

    // 6: output projection (fp32 out)
    {
        dim3 gO(Hh / 128, (Bb * Ss) / 128);
        gemm_out<<<gO, 256, H_SMEM>>>(bo, out);
    }
}